// round 1
// baseline (speedup 1.0000x reference)
#include <cuda_runtime.h>
#include <math.h>

#define NDEPTH 25
#define NDIM   64
#define NHID   100
#define NBATCH 262144
#define DT     (1.0f/25.0f)

// ---------------- smem layout (floats) ----------------
#define OFF_WD    0            // W_down   64x64
#define OFF_WDR   4096         // W_drift  64x64
#define OFF_W1    8192         // W1       64x100
#define OFF_BD    14592        // b_down   64
#define OFF_BDR   14656        // b_drift  64
#define OFF_B1    14720        // b1       100 (pad to 104)
#define OFF_W2    14824        // W2       100 (pad to 104)
#define OFF_B2    14928        // b2       1   (pad to 4)
#define OFF_NOISE 14932        // noise    25x64
#define OFF_X     16532        // stage    256 rows x pitch 68
#define X_PITCH   68
#define SMEM_FLOATS (OFF_X + 256*X_PITCH)
#define SMEM_BYTES  (SMEM_FLOATS*4)

// Lévy noise table (25*64), filled by prologue kernel
__device__ float g_noise[NDEPTH*NDIM];

// ---------------- packed fp32x2 helpers ----------------
__device__ __forceinline__ unsigned long long ffma2(unsigned long long a,
                                                    unsigned long long b,
                                                    unsigned long long c) {
    unsigned long long d;
    asm("fma.rn.f32x2 %0, %1, %2, %3;" : "=l"(d) : "l"(a), "l"(b), "l"(c));
    return d;
}
__device__ __forceinline__ unsigned long long pack2(float x) {
    unsigned long long r;
    asm("mov.b64 %0, {%1, %1};" : "=l"(r) : "r"(__float_as_uint(x)));
    return r;
}
__device__ __forceinline__ float2 unpack2(unsigned long long v) {
    unsigned int lo, hi;
    asm("mov.b64 {%0, %1}, %2;" : "=r"(lo), "=r"(hi) : "l"(v));
    float2 f;
    f.x = __uint_as_float(lo);
    f.y = __uint_as_float(hi);
    return f;
}

// ---------------- Chambers-Mallows-Stuck noise (fp64 for safety) ----------------
__global__ void noise_kernel(const float* __restrict__ u_raw,
                             const float* __restrict__ w_raw) {
    int i = blockIdx.x * blockDim.x + threadIdx.x;
    if (i >= NDEPTH * NDIM) return;
    double u = (double)u_raw[i];
    double w = (double)w_raw[i];
    double U = 3.14159265358979323846 * (u - 0.5);
    double wc = w;
    if (wc < 1e-12) wc = 1e-12;
    if (wc > 1.0)   wc = 1.0;
    double Wv = -log(wc);
    if (Wv < 1e-12) Wv = 1e-12;
    const double inv_a = 1.0 / 1.8;
    double X = (sin(1.8 * U) / pow(cos(U), inv_a))
             * pow(cos(U - 1.8 * U) / Wv, (1.0 - 1.8) * inv_a);
    double n = 0.1 * X;
    if (n >  10.0) n =  10.0;
    if (n < -10.0) n = -10.0;
    g_noise[i] = (float)n;
}

// ---------------- main: one thread per row, state in registers ----------------
__global__ __launch_bounds__(256, 1)
void sdenet_kernel(const float* __restrict__ x,
                   const float* __restrict__ W_down,  const float* __restrict__ b_down,
                   const float* __restrict__ W_drift, const float* __restrict__ b_drift,
                   const float* __restrict__ W1,      const float* __restrict__ b1,
                   const float* __restrict__ W2,      const float* __restrict__ b2,
                   float* __restrict__ out) {
    extern __shared__ float sm[];
    const int tid = threadIdx.x;

    // ---- cooperative weight load (L2-resident after first wave) ----
    for (int i = tid; i < 4096; i += 256) {
        sm[OFF_WD  + i] = W_down[i];
        sm[OFF_WDR + i] = W_drift[i];
    }
    for (int i = tid; i < 6400; i += 256) sm[OFF_W1 + i] = W1[i];
    if (tid < 64)  { sm[OFF_BD  + tid] = b_down[tid];  sm[OFF_BDR + tid] = b_drift[tid]; }
    if (tid < 100) { sm[OFF_B1  + tid] = b1[tid];      sm[OFF_W2  + tid] = W2[tid]; }
    if (tid == 0)    sm[OFF_B2] = b2[0];
    for (int i = tid; i < NDEPTH * NDIM; i += 256) sm[OFF_NOISE + i] = g_noise[i];

    // ---- stage x tile through smem (coalesced global <-> padded smem) ----
    const float* xb = x + (size_t)blockIdx.x * (256 * 64);
    for (int i = 4 * tid; i < 256 * 64; i += 1024) {
        float4 v = *(const float4*)(xb + i);
        int r = i >> 6, c = i & 63;
        *(float4*)&sm[OFF_X + r * X_PITCH + c] = v;
    }
    __syncthreads();

    // per-thread row state
    float s[64];
#pragma unroll
    for (int q = 0; q < 16; q++) {
        float4 v = *(const float4*)&sm[OFF_X + tid * X_PITCH + 4 * q];
        s[4*q] = v.x; s[4*q+1] = v.y; s[4*q+2] = v.z; s[4*q+3] = v.w;
    }

    const float dtpow = powf(DT, 1.0f / 1.8f);
    float scale = 0.0f;

    // st = -1 : W_down projection (+ MLP -> scale)
    // st = 0..24 : drift steps
    // st = 25 : final drift -> staging buffer
#pragma unroll 1
    for (int st = -1; st <= NDEPTH; st++) {
        const float* Wp = (st < 0) ? &sm[OFF_WD]  : &sm[OFF_WDR];
        const float* bp = (st < 0) ? &sm[OFF_BD]  : &sm[OFF_BDR];

        unsigned long long acc[32];
#pragma unroll
        for (int j = 0; j < 32; j++)
            acc[j] = ((const unsigned long long*)bp)[j];

#pragma unroll
        for (int k = 0; k < 64; k++) {
            unsigned long long sk = pack2(s[k]);
            const ulonglong2* wr = (const ulonglong2*)(Wp + k * 64);
#pragma unroll
            for (int q = 0; q < 16; q++) {
                ulonglong2 w = wr[q];
                acc[2*q]   = ffma2(sk, w.x, acc[2*q]);
                acc[2*q+1] = ffma2(sk, w.y, acc[2*q+1]);
            }
        }

        if (st < 0) {
            // state = x @ W_down + b_down
#pragma unroll
            for (int j = 0; j < 32; j++) {
                float2 v = unpack2(acc[j]);
                s[2*j] = v.x; s[2*j+1] = v.y;
            }
            // diffusion MLP on initial state -> per-row scale
            float logit = sm[OFF_B2];
#pragma unroll 1
            for (int jb = 0; jb < NHID; jb += 4) {
                unsigned long long a0 = ((const unsigned long long*)&sm[OFF_B1 + jb])[0];
                unsigned long long a1 = ((const unsigned long long*)&sm[OFF_B1 + jb])[1];
#pragma unroll
                for (int k = 0; k < 64; k++) {
                    unsigned long long sk = pack2(s[k]);
                    ulonglong2 w = *(const ulonglong2*)&sm[OFF_W1 + k * NHID + jb];
                    a0 = ffma2(sk, w.x, a0);
                    a1 = ffma2(sk, w.y, a1);
                }
                float2 v0 = unpack2(a0), v1 = unpack2(a1);
                float4 w2 = *(const float4*)&sm[OFF_W2 + jb];
                logit += fmaxf(v0.x, 0.f) * w2.x + fmaxf(v0.y, 0.f) * w2.y
                       + fmaxf(v1.x, 0.f) * w2.z + fmaxf(v1.y, 0.f) * w2.w;
            }
            scale = 0.5f * (1.0f / (1.0f + expf(-logit))) * dtpow;
        } else if (st < NDEPTH) {
            const float* np = &sm[OFF_NOISE + st * 64];
#pragma unroll
            for (int j = 0; j < 32; j++) {
                float2 v = unpack2(acc[j]);
                float r0 = fmaxf(v.x, 0.f);
                float r1 = fmaxf(v.y, 0.f);
                // out = out + (relu + out)*dt + scale*noise
                s[2*j]   = fmaf(r0 + s[2*j],   DT, s[2*j])   + scale * np[2*j];
                s[2*j+1] = fmaf(r1 + s[2*j+1], DT, s[2*j+1]) + scale * np[2*j+1];
            }
        } else {
            // final drift_out = relu(out@W+b) + out -> staging (own row only)
#pragma unroll
            for (int j = 0; j < 32; j++) {
                float2 v = unpack2(acc[j]);
                sm[OFF_X + tid * X_PITCH + 2*j]     = fmaxf(v.x, 0.f) + s[2*j];
                sm[OFF_X + tid * X_PITCH + 2*j + 1] = fmaxf(v.y, 0.f) + s[2*j+1];
            }
        }
    }

    // ---- write drift_out (coalesced via staging) ----
    __syncthreads();
    float* dout0 = out + (size_t)blockIdx.x * (256 * 64);
    for (int i = 4 * tid; i < 256 * 64; i += 1024) {
        int r = i >> 6, c = i & 63;
        *(float4*)(dout0 + i) = *(const float4*)&sm[OFF_X + r * X_PITCH + c];
    }
    __syncthreads();

    // ---- stage + write final state ----
#pragma unroll
    for (int q = 0; q < 16; q++) {
        *(float4*)&sm[OFF_X + tid * X_PITCH + 4 * q] =
            make_float4(s[4*q], s[4*q+1], s[4*q+2], s[4*q+3]);
    }
    __syncthreads();
    float* dout1 = out + (size_t)NBATCH * 64 + (size_t)blockIdx.x * (256 * 64);
    for (int i = 4 * tid; i < 256 * 64; i += 1024) {
        int r = i >> 6, c = i & 63;
        *(float4*)(dout1 + i) = *(const float4*)&sm[OFF_X + r * X_PITCH + c];
    }
}

extern "C" void kernel_launch(void* const* d_in, const int* in_sizes, int n_in,
                              void* d_out, int out_size) {
    const float* x       = (const float*)d_in[0];
    const float* u_raw   = (const float*)d_in[1];
    const float* w_raw   = (const float*)d_in[2];
    const float* W_down  = (const float*)d_in[3];
    const float* b_down  = (const float*)d_in[4];
    const float* W_drift = (const float*)d_in[5];
    const float* b_drift = (const float*)d_in[6];
    const float* W1      = (const float*)d_in[7];
    const float* b1      = (const float*)d_in[8];
    const float* W2      = (const float*)d_in[9];
    const float* b2      = (const float*)d_in[10];
    float* out = (float*)d_out;

    noise_kernel<<<(NDEPTH * NDIM + 255) / 256, 256>>>(u_raw, w_raw);

    cudaFuncSetAttribute(sdenet_kernel,
                         cudaFuncAttributeMaxDynamicSharedMemorySize, SMEM_BYTES);
    sdenet_kernel<<<NBATCH / 256, 256, SMEM_BYTES>>>(
        x, W_down, b_down, W_drift, b_drift, W1, b1, W2, b2, out);
}

// round 3
// speedup vs baseline: 2.5141x; 2.5141x over previous
#include <cuda_runtime.h>
#include <cuda_bf16.h>
#include <math.h>
#include <stdint.h>

#define NDEPTH 25
#define DT     (1.0f/25.0f)
#define NBATCH 262144
#define TILE_M 128

// ---------------- smem float-index offsets ----------------
#define F_WDOWN  0            // 64x64
#define F_WDRIFT 4096         // 64x64
#define F_W1     8192         // 64x104 (padded)
#define F_NOISE  14848        // 25x64
#define F_BD     16448        // 64
#define F_BDR    16512        // 64
#define F_B1     16576        // 104 (padded w/ 0)
#define F_W2     16680        // 104 (padded w/ 0)
#define F_B2     16784        // 1 (pad 4)
#define F_BLO    16788        // 64 frags x 32 lanes (u32)
#define F_STAGE  18836        // 128 rows x pitch 68
#define ST_PITCH 68
#define F_TOTAL  (F_STAGE + 128*ST_PITCH)
#define SMEM_BYTES (F_TOTAL*4)        // 110160 B

__device__ float g_noise[NDEPTH*64];

// ---------------- helpers ----------------
// pack two fp32 -> bf16x2 (e0 in low half = even index)
__device__ __forceinline__ uint32_t pk(float e0, float e1) {
    uint32_t r;
    asm("cvt.rn.bf16x2.f32 %0, %1, %2;" : "=r"(r) : "f"(e1), "f"(e0));
    return r;
}
__device__ __forceinline__ float bf_lo(uint32_t p) { return __uint_as_float(p << 16); }
__device__ __forceinline__ float bf_hi(uint32_t p) { return __uint_as_float(p & 0xffff0000u); }

// split (v0,v1) into hi bf16x2 and residual-lo bf16x2
__device__ __forceinline__ void split2(float v0, float v1, uint32_t& hi, uint32_t& lo) {
    hi = pk(v0, v1);
    lo = pk(v0 - bf_lo(hi), v1 - bf_hi(hi));
}

__device__ __forceinline__ void mma16816(float* c,
                                         uint32_t a0, uint32_t a1, uint32_t a2, uint32_t a3,
                                         uint32_t b0, uint32_t b1) {
    asm volatile(
        "mma.sync.aligned.m16n8k16.row.col.f32.bf16.bf16.f32 "
        "{%0,%1,%2,%3}, {%4,%5,%6,%7}, {%8,%9}, {%0,%1,%2,%3};"
        : "+f"(c[0]), "+f"(c[1]), "+f"(c[2]), "+f"(c[3])
        : "r"(a0), "r"(a1), "r"(a2), "r"(a3), "r"(b0), "r"(b1));
}

// ---------------- Lévy noise prologue (fp64) ----------------
__global__ void noise_kernel(const float* __restrict__ u_raw,
                             const float* __restrict__ w_raw) {
    int i = blockIdx.x * blockDim.x + threadIdx.x;
    if (i >= NDEPTH * 64) return;
    double u = (double)u_raw[i];
    double w = (double)w_raw[i];
    double U = 3.14159265358979323846 * (u - 0.5);
    double wc = w; if (wc < 1e-12) wc = 1e-12; if (wc > 1.0) wc = 1.0;
    double Wv = -log(wc); if (Wv < 1e-12) Wv = 1e-12;
    const double inv_a = 1.0 / 1.8;
    double X = (sin(1.8 * U) / pow(cos(U), inv_a))
             * pow(cos(U - 1.8 * U) / Wv, (1.0 - 1.8) * inv_a);
    double n = 0.1 * X;
    if (n >  10.0) n =  10.0;
    if (n < -10.0) n = -10.0;
    g_noise[i] = (float)n;
}

// ---------------- main: warp-level mma chained GEMM ----------------
// 256 threads = 8 warps; warp w owns rows 16w..16w+15 of a 128-row tile.
// Thread state: d[8][4] = D fragments of s [16 x 64] (8 n-tiles of m16n8).
__global__ void __launch_bounds__(256, 1)
sdenet_mma(const float* __restrict__ x,
           const float* __restrict__ W_down,  const float* __restrict__ b_down,
           const float* __restrict__ W_drift, const float* __restrict__ b_drift,
           const float* __restrict__ W1,      const float* __restrict__ b1,
           const float* __restrict__ W2,      const float* __restrict__ b2,
           float* __restrict__ out) {
    extern __shared__ float sm[];
    const int tid  = threadIdx.x;
    const int wid  = tid >> 5;
    const int lane = tid & 31;
    const int quad = lane >> 2;   // groupID (row within 8)
    const int qt   = lane & 3;    // thread-in-group (col pair selector)

    // ---- cooperative loads ----
    for (int i = tid; i < 4096; i += 256) {
        sm[F_WDOWN  + i] = W_down[i];
        sm[F_WDRIFT + i] = W_drift[i];
    }
    for (int i = tid; i < 64 * 104; i += 256) {
        int k = i / 104, n = i % 104;
        sm[F_W1 + i] = (n < 100) ? W1[k * 100 + n] : 0.0f;
    }
    for (int i = tid; i < NDEPTH * 64; i += 256) sm[F_NOISE + i] = g_noise[i];
    if (tid < 64)  { sm[F_BD + tid] = b_down[tid]; sm[F_BDR + tid] = b_drift[tid]; }
    if (tid < 104) {
        sm[F_B1 + tid] = (tid < 100) ? b1[tid] : 0.0f;
        sm[F_W2 + tid] = (tid < 100) ? W2[tid] : 0.0f;
    }
    if (tid == 0) sm[F_B2] = b2[0];

    // x tile -> stage (coalesced)
    const float* xb = x + (size_t)blockIdx.x * (TILE_M * 64);
    for (int i = 4 * tid; i < TILE_M * 64; i += 1024) {
        float4 v = *(const float4*)(xb + i);
        int r = i >> 6, c = i & 63;
        *(float4*)&sm[F_STAGE + r * ST_PITCH + c] = v;
    }
    __syncthreads();

    // ---- W_drift B-fragments: hi in regs (64), lo in smem (64x32 u32) ----
    uint32_t bh[64];
#pragma unroll
    for (int nt = 0; nt < 8; nt++)
#pragma unroll
        for (int kt = 0; kt < 4; kt++)
#pragma unroll
            for (int h = 0; h < 2; h++) {
                int n = quad + 8 * nt;
                int k = 16 * kt + 2 * qt + 8 * h;
                uint32_t hi, lo;
                split2(sm[F_WDRIFT + k * 64 + n], sm[F_WDRIFT + (k + 1) * 64 + n], hi, lo);
                int f = (nt * 4 + kt) * 2 + h;
                bh[f] = hi;
                if (wid == 0)
                    *(uint32_t*)&sm[F_BLO + f * 32 + lane] = lo;
            }
    // drift bias per accumulator column position
    float bdr0[8], bdr1[8];
#pragma unroll
    for (int nt = 0; nt < 8; nt++) {
        int c0 = 8 * nt + 2 * qt;
        bdr0[nt] = sm[F_BDR + c0];
        bdr1[nt] = sm[F_BDR + c0 + 1];
    }
    __syncthreads();   // publish F_BLO

    const int row0 = 16 * wid + quad;

    // ---- A fragments of x (hi/lo) ----
    uint32_t ah[16], al[16];
#pragma unroll
    for (int kt = 0; kt < 4; kt++) {
        int k0 = 16 * kt + 2 * qt;
        const float* r0p = &sm[F_STAGE + row0 * ST_PITCH];
        const float* r1p = &sm[F_STAGE + (row0 + 8) * ST_PITCH];
        split2(r0p[k0],     r0p[k0 + 1], ah[4*kt + 0], al[4*kt + 0]);
        split2(r1p[k0],     r1p[k0 + 1], ah[4*kt + 1], al[4*kt + 1]);
        split2(r0p[k0 + 8], r0p[k0 + 9], ah[4*kt + 2], al[4*kt + 2]);
        split2(r1p[k0 + 8], r1p[k0 + 9], ah[4*kt + 3], al[4*kt + 3]);
    }

    // ---- GEMM1: s = x @ W_down + b_down (B built on the fly) ----
    float d[8][4];
#pragma unroll
    for (int nt = 0; nt < 8; nt++) {
        int c0 = 8 * nt + 2 * qt;
        float c[4] = { sm[F_BD + c0], sm[F_BD + c0 + 1], sm[F_BD + c0], sm[F_BD + c0 + 1] };
        int n = quad + 8 * nt;
#pragma unroll
        for (int kt = 0; kt < 4; kt++) {
            int k = 16 * kt + 2 * qt;
            uint32_t b0h, b0l, b1h, b1l;
            split2(sm[F_WDOWN + k * 64 + n],       sm[F_WDOWN + (k + 1) * 64 + n], b0h, b0l);
            split2(sm[F_WDOWN + (k + 8) * 64 + n], sm[F_WDOWN + (k + 9) * 64 + n], b1h, b1l);
            mma16816(c, ah[4*kt], ah[4*kt+1], ah[4*kt+2], ah[4*kt+3], b0h, b1h);
            mma16816(c, al[4*kt], al[4*kt+1], al[4*kt+2], al[4*kt+3], b0h, b1h);
            mma16816(c, ah[4*kt], ah[4*kt+1], ah[4*kt+2], ah[4*kt+3], b0l, b1l);
        }
        d[nt][0] = c[0]; d[nt][1] = c[1]; d[nt][2] = c[2]; d[nt][3] = c[3];
    }

    // rebuild A fragments from state (D layout == A layout, zero shuffles)
#pragma unroll
    for (int kt = 0; kt < 4; kt++) {
        split2(d[2*kt][0],   d[2*kt][1],   ah[4*kt + 0], al[4*kt + 0]);
        split2(d[2*kt][2],   d[2*kt][3],   ah[4*kt + 1], al[4*kt + 1]);
        split2(d[2*kt+1][0], d[2*kt+1][1], ah[4*kt + 2], al[4*kt + 2]);
        split2(d[2*kt+1][2], d[2*kt+1][3], ah[4*kt + 3], al[4*kt + 3]);
    }

    // ---- diffusion MLP: logit = relu(s@W1 + b1)@W2 + b2 (W1 padded to 104) ----
    float p0 = 0.0f, p1 = 0.0f;
#pragma unroll
    for (int nt = 0; nt < 13; nt++) {
        float c[4] = {0.f, 0.f, 0.f, 0.f};
        int n = quad + 8 * nt;
#pragma unroll
        for (int kt = 0; kt < 4; kt++) {
            int k = 16 * kt + 2 * qt;
            uint32_t b0h, b0l, b1h, b1l;
            split2(sm[F_W1 + k * 104 + n],       sm[F_W1 + (k + 1) * 104 + n], b0h, b0l);
            split2(sm[F_W1 + (k + 8) * 104 + n], sm[F_W1 + (k + 9) * 104 + n], b1h, b1l);
            mma16816(c, ah[4*kt], ah[4*kt+1], ah[4*kt+2], ah[4*kt+3], b0h, b1h);
            mma16816(c, al[4*kt], al[4*kt+1], al[4*kt+2], al[4*kt+3], b0h, b1h);
            mma16816(c, ah[4*kt], ah[4*kt+1], ah[4*kt+2], ah[4*kt+3], b0l, b1l);
        }
        int c0 = 8 * nt + 2 * qt;
        float w20 = sm[F_W2 + c0], w21 = sm[F_W2 + c0 + 1];
        float bb0 = sm[F_B1 + c0], bb1 = sm[F_B1 + c0 + 1];
        p0 += fmaxf(c[0] + bb0, 0.f) * w20 + fmaxf(c[1] + bb1, 0.f) * w21;
        p1 += fmaxf(c[2] + bb0, 0.f) * w20 + fmaxf(c[3] + bb1, 0.f) * w21;
    }
    p0 += __shfl_xor_sync(0xffffffffu, p0, 1);
    p0 += __shfl_xor_sync(0xffffffffu, p0, 2);
    p1 += __shfl_xor_sync(0xffffffffu, p1, 1);
    p1 += __shfl_xor_sync(0xffffffffu, p1, 2);
    const float dtpow = powf(DT, 1.0f / 1.8f);
    const float b2v = sm[F_B2];
    const float scale0 = 0.5f * dtpow / (1.0f + expf(-(p0 + b2v)));
    const float scale1 = 0.5f * dtpow / (1.0f + expf(-(p1 + b2v)));

    // ---- 26 drift steps (last produces drift_out into stage) ----
    const uint32_t* blo = (const uint32_t*)&sm[F_BLO] + lane;
#pragma unroll 1
    for (int st = 0; st < 26; st++) {
#pragma unroll
        for (int nt = 0; nt < 8; nt++) {
            float c[4] = { bdr0[nt], bdr1[nt], bdr0[nt], bdr1[nt] };
#pragma unroll
            for (int kt = 0; kt < 4; kt++) {
                int f = (nt * 4 + kt) * 2;
                uint32_t b0 = bh[f], b1 = bh[f + 1];
                uint32_t l0 = blo[f * 32], l1 = blo[(f + 1) * 32];
                mma16816(c, ah[4*kt], ah[4*kt+1], ah[4*kt+2], ah[4*kt+3], b0, b1);
                mma16816(c, al[4*kt], al[4*kt+1], al[4*kt+2], al[4*kt+3], b0, b1);
                mma16816(c, ah[4*kt], ah[4*kt+1], ah[4*kt+2], ah[4*kt+3], l0, l1);
            }
            int c0col = 8 * nt + 2 * qt;
            if (st < NDEPTH) {
                float n0 = sm[F_NOISE + st * 64 + c0col];
                float n1 = sm[F_NOISE + st * 64 + c0col + 1];
                float r0 = fmaxf(c[0], 0.f), r1 = fmaxf(c[1], 0.f);
                float r2 = fmaxf(c[2], 0.f), r3 = fmaxf(c[3], 0.f);
                d[nt][0] = fmaf(r0 + d[nt][0], DT, d[nt][0]) + scale0 * n0;
                d[nt][1] = fmaf(r1 + d[nt][1], DT, d[nt][1]) + scale0 * n1;
                d[nt][2] = fmaf(r2 + d[nt][2], DT, d[nt][2]) + scale1 * n0;
                d[nt][3] = fmaf(r3 + d[nt][3], DT, d[nt][3]) + scale1 * n1;
            } else {
                // drift_out = relu(out@W+b) + out  -> stage (own rows only)
                sm[F_STAGE + row0 * ST_PITCH + c0col]           = fmaxf(c[0], 0.f) + d[nt][0];
                sm[F_STAGE + row0 * ST_PITCH + c0col + 1]       = fmaxf(c[1], 0.f) + d[nt][1];
                sm[F_STAGE + (row0 + 8) * ST_PITCH + c0col]     = fmaxf(c[2], 0.f) + d[nt][2];
                sm[F_STAGE + (row0 + 8) * ST_PITCH + c0col + 1] = fmaxf(c[3], 0.f) + d[nt][3];
            }
        }
        if (st < NDEPTH) {
            // rebuild A fragments from updated state
#pragma unroll
            for (int kt = 0; kt < 4; kt++) {
                split2(d[2*kt][0],   d[2*kt][1],   ah[4*kt + 0], al[4*kt + 0]);
                split2(d[2*kt][2],   d[2*kt][3],   ah[4*kt + 1], al[4*kt + 1]);
                split2(d[2*kt+1][0], d[2*kt+1][1], ah[4*kt + 2], al[4*kt + 2]);
                split2(d[2*kt+1][2], d[2*kt+1][3], ah[4*kt + 3], al[4*kt + 3]);
            }
        }
    }

    // ---- write drift_out (coalesced via stage) ----
    __syncthreads();
    float* o0 = out + (size_t)blockIdx.x * (TILE_M * 64);
    for (int i = 4 * tid; i < TILE_M * 64; i += 1024) {
        int r = i >> 6, c = i & 63;
        *(float4*)(o0 + i) = *(const float4*)&sm[F_STAGE + r * ST_PITCH + c];
    }
    __syncthreads();

    // ---- stage + write final state ----
#pragma unroll
    for (int nt = 0; nt < 8; nt++) {
        int c0col = 8 * nt + 2 * qt;
        sm[F_STAGE + row0 * ST_PITCH + c0col]           = d[nt][0];
        sm[F_STAGE + row0 * ST_PITCH + c0col + 1]       = d[nt][1];
        sm[F_STAGE + (row0 + 8) * ST_PITCH + c0col]     = d[nt][2];
        sm[F_STAGE + (row0 + 8) * ST_PITCH + c0col + 1] = d[nt][3];
    }
    __syncthreads();
    float* o1 = out + (size_t)NBATCH * 64 + (size_t)blockIdx.x * (TILE_M * 64);
    for (int i = 4 * tid; i < TILE_M * 64; i += 1024) {
        int r = i >> 6, c = i & 63;
        *(float4*)(o1 + i) = *(const float4*)&sm[F_STAGE + r * ST_PITCH + c];
    }
}

extern "C" void kernel_launch(void* const* d_in, const int* in_sizes, int n_in,
                              void* d_out, int out_size) {
    const float* x       = (const float*)d_in[0];
    const float* u_raw   = (const float*)d_in[1];
    const float* w_raw   = (const float*)d_in[2];
    const float* W_down  = (const float*)d_in[3];
    const float* b_down  = (const float*)d_in[4];
    const float* W_drift = (const float*)d_in[5];
    const float* b_drift = (const float*)d_in[6];
    const float* W1      = (const float*)d_in[7];
    const float* b1      = (const float*)d_in[8];
    const float* W2      = (const float*)d_in[9];
    const float* b2      = (const float*)d_in[10];
    float* out = (float*)d_out;

    noise_kernel<<<(NDEPTH * 64 + 255) / 256, 256>>>(u_raw, w_raw);

    cudaFuncSetAttribute(sdenet_mma,
                         cudaFuncAttributeMaxDynamicSharedMemorySize, SMEM_BYTES);
    sdenet_mma<<<NBATCH / TILE_M, 256, SMEM_BYTES>>>(
        x, W_down, b_down, W_drift, b_drift, W1, b1, W2, b2, out);
}

// round 4
// speedup vs baseline: 3.3326x; 1.3256x over previous
#include <cuda_runtime.h>
#include <cuda_bf16.h>
#include <math.h>
#include <stdint.h>

#define NDEPTH 25
#define DT     (1.0f/25.0f)
#define NBATCH 262144
#define TILE_M 256
#define NTHREADS 512

// ---------------- smem float-index offsets ----------------
#define F_WDOWN  0            // 64x64
#define F_WDRIFT 4096         // 64x64
#define F_W1     8192         // 64x104 (padded)
#define F_NOISE  14848        // 25x64
#define F_BD     16448        // 64
#define F_BDR    16512        // 64
#define F_B1     16576        // 104
#define F_W2     16680        // 104
#define F_B2     16784        // 1 (pad 4)
#define F_B4     16788        // 32 groups x 32 lanes x uint4 (16B aligned: 67152B)
#define F_STAGE  20884        // 256 rows x pitch 68
#define ST_PITCH 68
#define F_TOTAL  (F_STAGE + 256*ST_PITCH)
#define SMEM_BYTES (F_TOTAL*4)        // 153168 B

__device__ float g_noise[NDEPTH*64];

// ---------------- helpers ----------------
__device__ __forceinline__ uint32_t pk(float e0, float e1) {
    uint32_t r;
    asm("cvt.rn.bf16x2.f32 %0, %1, %2;" : "=r"(r) : "f"(e1), "f"(e0));
    return r;
}
__device__ __forceinline__ float bf_lo(uint32_t p) { return __uint_as_float(p << 16); }
__device__ __forceinline__ float bf_hi(uint32_t p) { return __uint_as_float(p & 0xffff0000u); }

__device__ __forceinline__ void split2(float v0, float v1, uint32_t& hi, uint32_t& lo) {
    hi = pk(v0, v1);
    lo = pk(v0 - bf_lo(hi), v1 - bf_hi(hi));
}

__device__ __forceinline__ void mma16816(float* c,
                                         uint32_t a0, uint32_t a1, uint32_t a2, uint32_t a3,
                                         uint32_t b0, uint32_t b1) {
    asm volatile(
        "mma.sync.aligned.m16n8k16.row.col.f32.bf16.bf16.f32 "
        "{%0,%1,%2,%3}, {%4,%5,%6,%7}, {%8,%9}, {%0,%1,%2,%3};"
        : "+f"(c[0]), "+f"(c[1]), "+f"(c[2]), "+f"(c[3])
        : "r"(a0), "r"(a1), "r"(a2), "r"(a3), "r"(b0), "r"(b1));
}

// ---------------- Lévy noise prologue (fp64) ----------------
__global__ void noise_kernel(const float* __restrict__ u_raw,
                             const float* __restrict__ w_raw) {
    int i = blockIdx.x * blockDim.x + threadIdx.x;
    if (i >= NDEPTH * 64) return;
    double u = (double)u_raw[i];
    double w = (double)w_raw[i];
    double U = 3.14159265358979323846 * (u - 0.5);
    double wc = w; if (wc < 1e-12) wc = 1e-12; if (wc > 1.0) wc = 1.0;
    double Wv = -log(wc); if (Wv < 1e-12) Wv = 1e-12;
    const double inv_a = 1.0 / 1.8;
    double X = (sin(1.8 * U) / pow(cos(U), inv_a))
             * pow(cos(U - 1.8 * U) / Wv, (1.0 - 1.8) * inv_a);
    double n = 0.1 * X;
    if (n >  10.0) n =  10.0;
    if (n < -10.0) n = -10.0;
    g_noise[i] = (float)n;
}

// ---------------- main: 16 warps, warp w owns rows 16w..16w+15 ----------------
__global__ void __launch_bounds__(NTHREADS, 1)
sdenet_mma(const float* __restrict__ x,
           const float* __restrict__ W_down,  const float* __restrict__ b_down,
           const float* __restrict__ W_drift, const float* __restrict__ b_drift,
           const float* __restrict__ W1,      const float* __restrict__ b1,
           const float* __restrict__ W2,      const float* __restrict__ b2,
           float* __restrict__ out) {
    extern __shared__ float sm[];
    const int tid  = threadIdx.x;
    const int wid  = tid >> 5;
    const int lane = tid & 31;
    const int quad = lane >> 2;
    const int qt   = lane & 3;

    // ---- cooperative loads ----
    for (int i = tid; i < 4096; i += NTHREADS) {
        sm[F_WDOWN  + i] = W_down[i];
        sm[F_WDRIFT + i] = W_drift[i];
    }
    for (int i = tid; i < 64 * 104; i += NTHREADS) {
        int k = i / 104, n = i % 104;
        sm[F_W1 + i] = (n < 100) ? W1[k * 100 + n] : 0.0f;
    }
    for (int i = tid; i < NDEPTH * 64; i += NTHREADS) sm[F_NOISE + i] = g_noise[i];
    if (tid < 64)  { sm[F_BD + tid] = b_down[tid]; sm[F_BDR + tid] = b_drift[tid]; }
    if (tid < 104) {
        sm[F_B1 + tid] = (tid < 100) ? b1[tid] : 0.0f;
        sm[F_W2 + tid] = (tid < 100) ? W2[tid] : 0.0f;
    }
    if (tid == 0) sm[F_B2] = b2[0];

    // x tile -> stage (coalesced)
    const float* xb = x + (size_t)blockIdx.x * (TILE_M * 64);
    for (int i = 4 * tid; i < TILE_M * 64; i += 4 * NTHREADS) {
        float4 v = *(const float4*)(xb + i);
        int r = i >> 6, c = i & 63;
        *(float4*)&sm[F_STAGE + r * ST_PITCH + c] = v;
    }
    __syncthreads();

    // ---- W_drift B-fragment table (warp 0 builds): per (g=nt*4+kt, lane) uint4 {b0h,b1h,b0l,b1l} ----
    if (wid == 0) {
#pragma unroll
        for (int nt = 0; nt < 8; nt++)
#pragma unroll
            for (int kt = 0; kt < 4; kt++) {
                int n = quad + 8 * nt;
                int k = 16 * kt + 2 * qt;
                uint32_t b0h, b0l, b1h, b1l;
                split2(sm[F_WDRIFT + k * 64 + n],       sm[F_WDRIFT + (k + 1) * 64 + n], b0h, b0l);
                split2(sm[F_WDRIFT + (k + 8) * 64 + n], sm[F_WDRIFT + (k + 9) * 64 + n], b1h, b1l);
                int g = nt * 4 + kt;
                ((uint4*)&sm[F_B4])[g * 32 + lane] = make_uint4(b0h, b1h, b0l, b1l);
            }
    }
    // drift bias per accumulator column position (constant across steps)
    float bdr0[8], bdr1[8];
#pragma unroll
    for (int nt = 0; nt < 8; nt++) {
        int c0 = 8 * nt + 2 * qt;
        bdr0[nt] = sm[F_BDR + c0];
        bdr1[nt] = sm[F_BDR + c0 + 1];
    }
    __syncthreads();   // publish F_B4

    const int row0 = 16 * wid + quad;

    // ---- A fragments of x (hi/lo) ----
    uint32_t ah[16], al[16];
#pragma unroll
    for (int kt = 0; kt < 4; kt++) {
        int k0 = 16 * kt + 2 * qt;
        const float* r0p = &sm[F_STAGE + row0 * ST_PITCH];
        const float* r1p = &sm[F_STAGE + (row0 + 8) * ST_PITCH];
        split2(r0p[k0],     r0p[k0 + 1], ah[4*kt + 0], al[4*kt + 0]);
        split2(r1p[k0],     r1p[k0 + 1], ah[4*kt + 1], al[4*kt + 1]);
        split2(r0p[k0 + 8], r0p[k0 + 9], ah[4*kt + 2], al[4*kt + 2]);
        split2(r1p[k0 + 8], r1p[k0 + 9], ah[4*kt + 3], al[4*kt + 3]);
    }

    // ---- GEMM1: s = x @ W_down + b_down (B built on the fly) ----
    float d[8][4];
#pragma unroll
    for (int nt = 0; nt < 8; nt++) {
        int c0 = 8 * nt + 2 * qt;
        float c[4] = { sm[F_BD + c0], sm[F_BD + c0 + 1], sm[F_BD + c0], sm[F_BD + c0 + 1] };
        int n = quad + 8 * nt;
#pragma unroll
        for (int kt = 0; kt < 4; kt++) {
            int k = 16 * kt + 2 * qt;
            uint32_t b0h, b0l, b1h, b1l;
            split2(sm[F_WDOWN + k * 64 + n],       sm[F_WDOWN + (k + 1) * 64 + n], b0h, b0l);
            split2(sm[F_WDOWN + (k + 8) * 64 + n], sm[F_WDOWN + (k + 9) * 64 + n], b1h, b1l);
            mma16816(c, ah[4*kt], ah[4*kt+1], ah[4*kt+2], ah[4*kt+3], b0h, b1h);
            mma16816(c, al[4*kt], al[4*kt+1], al[4*kt+2], al[4*kt+3], b0h, b1h);
            mma16816(c, ah[4*kt], ah[4*kt+1], ah[4*kt+2], ah[4*kt+3], b0l, b1l);
        }
        d[nt][0] = c[0]; d[nt][1] = c[1]; d[nt][2] = c[2]; d[nt][3] = c[3];
    }

    // rebuild A fragments from state (D layout == A layout)
#pragma unroll
    for (int kt = 0; kt < 4; kt++) {
        split2(d[2*kt][0],   d[2*kt][1],   ah[4*kt + 0], al[4*kt + 0]);
        split2(d[2*kt][2],   d[2*kt][3],   ah[4*kt + 1], al[4*kt + 1]);
        split2(d[2*kt+1][0], d[2*kt+1][1], ah[4*kt + 2], al[4*kt + 2]);
        split2(d[2*kt+1][2], d[2*kt+1][3], ah[4*kt + 3], al[4*kt + 3]);
    }

    // ---- diffusion MLP ----
    float p0 = 0.0f, p1 = 0.0f;
#pragma unroll
    for (int nt = 0; nt < 13; nt++) {
        float c[4] = {0.f, 0.f, 0.f, 0.f};
        int n = quad + 8 * nt;
#pragma unroll
        for (int kt = 0; kt < 4; kt++) {
            int k = 16 * kt + 2 * qt;
            uint32_t b0h, b0l, b1h, b1l;
            split2(sm[F_W1 + k * 104 + n],       sm[F_W1 + (k + 1) * 104 + n], b0h, b0l);
            split2(sm[F_W1 + (k + 8) * 104 + n], sm[F_W1 + (k + 9) * 104 + n], b1h, b1l);
            mma16816(c, ah[4*kt], ah[4*kt+1], ah[4*kt+2], ah[4*kt+3], b0h, b1h);
            mma16816(c, al[4*kt], al[4*kt+1], al[4*kt+2], al[4*kt+3], b0h, b1h);
            mma16816(c, ah[4*kt], ah[4*kt+1], ah[4*kt+2], ah[4*kt+3], b0l, b1l);
        }
        int c0 = 8 * nt + 2 * qt;
        float w20 = sm[F_W2 + c0], w21 = sm[F_W2 + c0 + 1];
        float bb0 = sm[F_B1 + c0], bb1 = sm[F_B1 + c0 + 1];
        p0 += fmaxf(c[0] + bb0, 0.f) * w20 + fmaxf(c[1] + bb1, 0.f) * w21;
        p1 += fmaxf(c[2] + bb0, 0.f) * w20 + fmaxf(c[3] + bb1, 0.f) * w21;
    }
    p0 += __shfl_xor_sync(0xffffffffu, p0, 1);
    p0 += __shfl_xor_sync(0xffffffffu, p0, 2);
    p1 += __shfl_xor_sync(0xffffffffu, p1, 1);
    p1 += __shfl_xor_sync(0xffffffffu, p1, 2);
    const float dtpow = powf(DT, 1.0f / 1.8f);
    const float b2v = sm[F_B2];
    const float scale0 = 0.5f * dtpow / (1.0f + expf(-(p0 + b2v)));
    const float scale1 = 0.5f * dtpow / (1.0f + expf(-(p1 + b2v)));

    // ---- 26 drift steps (last produces drift_out into stage) ----
    const uint4* tbl = (const uint4*)&sm[F_B4] + lane;
#pragma unroll 1
    for (int st = 0; st < 26; st++) {
#pragma unroll
        for (int nt = 0; nt < 8; nt++) {
            float c[4] = { bdr0[nt], bdr1[nt], bdr0[nt], bdr1[nt] };
#pragma unroll
            for (int kt = 0; kt < 4; kt++) {
                uint4 b = tbl[(nt * 4 + kt) * 32];
                mma16816(c, ah[4*kt], ah[4*kt+1], ah[4*kt+2], ah[4*kt+3], b.x, b.y);
                mma16816(c, al[4*kt], al[4*kt+1], al[4*kt+2], al[4*kt+3], b.x, b.y);
                mma16816(c, ah[4*kt], ah[4*kt+1], ah[4*kt+2], ah[4*kt+3], b.z, b.w);
            }
            int c0col = 8 * nt + 2 * qt;
            if (st < NDEPTH) {
                float2 nz = *(const float2*)&sm[F_NOISE + st * 64 + c0col];
                float r0 = fmaxf(c[0], 0.f), r1 = fmaxf(c[1], 0.f);
                float r2 = fmaxf(c[2], 0.f), r3 = fmaxf(c[3], 0.f);
                d[nt][0] = fmaf(r0 + d[nt][0], DT, d[nt][0]) + scale0 * nz.x;
                d[nt][1] = fmaf(r1 + d[nt][1], DT, d[nt][1]) + scale0 * nz.y;
                d[nt][2] = fmaf(r2 + d[nt][2], DT, d[nt][2]) + scale1 * nz.x;
                d[nt][3] = fmaf(r3 + d[nt][3], DT, d[nt][3]) + scale1 * nz.y;
            } else {
                sm[F_STAGE + row0 * ST_PITCH + c0col]           = fmaxf(c[0], 0.f) + d[nt][0];
                sm[F_STAGE + row0 * ST_PITCH + c0col + 1]       = fmaxf(c[1], 0.f) + d[nt][1];
                sm[F_STAGE + (row0 + 8) * ST_PITCH + c0col]     = fmaxf(c[2], 0.f) + d[nt][2];
                sm[F_STAGE + (row0 + 8) * ST_PITCH + c0col + 1] = fmaxf(c[3], 0.f) + d[nt][3];
            }
        }
        if (st < NDEPTH) {
#pragma unroll
            for (int kt = 0; kt < 4; kt++) {
                split2(d[2*kt][0],   d[2*kt][1],   ah[4*kt + 0], al[4*kt + 0]);
                split2(d[2*kt][2],   d[2*kt][3],   ah[4*kt + 1], al[4*kt + 1]);
                split2(d[2*kt+1][0], d[2*kt+1][1], ah[4*kt + 2], al[4*kt + 2]);
                split2(d[2*kt+1][2], d[2*kt+1][3], ah[4*kt + 3], al[4*kt + 3]);
            }
        }
    }

    // ---- write drift_out (coalesced via stage) ----
    __syncthreads();
    float* o0 = out + (size_t)blockIdx.x * (TILE_M * 64);
    for (int i = 4 * tid; i < TILE_M * 64; i += 4 * NTHREADS) {
        int r = i >> 6, c = i & 63;
        *(float4*)(o0 + i) = *(const float4*)&sm[F_STAGE + r * ST_PITCH + c];
    }
    __syncthreads();

    // ---- stage + write final state ----
#pragma unroll
    for (int nt = 0; nt < 8; nt++) {
        int c0col = 8 * nt + 2 * qt;
        sm[F_STAGE + row0 * ST_PITCH + c0col]           = d[nt][0];
        sm[F_STAGE + row0 * ST_PITCH + c0col + 1]       = d[nt][1];
        sm[F_STAGE + (row0 + 8) * ST_PITCH + c0col]     = d[nt][2];
        sm[F_STAGE + (row0 + 8) * ST_PITCH + c0col + 1] = d[nt][3];
    }
    __syncthreads();
    float* o1 = out + (size_t)NBATCH * 64 + (size_t)blockIdx.x * (TILE_M * 64);
    for (int i = 4 * tid; i < TILE_M * 64; i += 4 * NTHREADS) {
        int r = i >> 6, c = i & 63;
        *(float4*)(o1 + i) = *(const float4*)&sm[F_STAGE + r * ST_PITCH + c];
    }
}

extern "C" void kernel_launch(void* const* d_in, const int* in_sizes, int n_in,
                              void* d_out, int out_size) {
    const float* x       = (const float*)d_in[0];
    const float* u_raw   = (const float*)d_in[1];
    const float* w_raw   = (const float*)d_in[2];
    const float* W_down  = (const float*)d_in[3];
    const float* b_down  = (const float*)d_in[4];
    const float* W_drift = (const float*)d_in[5];
    const float* b_drift = (const float*)d_in[6];
    const float* W1      = (const float*)d_in[7];
    const float* b1      = (const float*)d_in[8];
    const float* W2      = (const float*)d_in[9];
    const float* b2      = (const float*)d_in[10];
    float* out = (float*)d_out;

    noise_kernel<<<(NDEPTH * 64 + 255) / 256, 256>>>(u_raw, w_raw);

    cudaFuncSetAttribute(sdenet_mma,
                         cudaFuncAttributeMaxDynamicSharedMemorySize, SMEM_BYTES);
    sdenet_mma<<<NBATCH / TILE_M, NTHREADS, SMEM_BYTES>>>(
        x, W_down, b_down, W_drift, b_drift, W1, b1, W2, b2, out);
}

// round 5
// speedup vs baseline: 3.4030x; 1.0211x over previous
#include <cuda_runtime.h>
#include <cuda_fp16.h>
#include <math.h>
#include <stdint.h>

#define NDEPTH 25
#define DT     (1.0f/25.0f)
#define NBATCH 262144
#define TILE_M 256
#define NTHREADS 512

// ---------------- smem float-index offsets ----------------
#define F_WDOWN  0            // 64x64
#define F_WDRIFT 4096         // 64x64
#define F_W1     8192         // 64x104 (padded)
#define F_NOISE  14848        // 25x64
#define F_BD     16448        // 64
#define F_BDR    16512        // 64
#define F_B1     16576        // 104
#define F_W2     16680        // 104
#define F_B2     16784        // 1 (pad 4)
#define F_BHI    16788        // 32 groups x 32 lanes x uint2 (hi frags, 8KB)
#define F_BLO    18836        // 32 groups x 32 lanes x uint2 (lo frags, 8KB)
#define F_STAGE  20884        // 256 rows x pitch 68
#define ST_PITCH 68
#define F_TOTAL  (F_STAGE + 256*ST_PITCH)
#define SMEM_BYTES (F_TOTAL*4)        // 153168 B

__device__ float g_noise[NDEPTH*64];

// ---------------- fp16 pack/split helpers ----------------
// pack two fp32 -> f16x2 (e0 in LOW half)
__device__ __forceinline__ uint32_t pkh(float e0, float e1) {
    uint32_t r;
    asm("cvt.rn.f16x2.f32 %0, %1, %2;" : "=r"(r) : "f"(e1), "f"(e0));
    return r;
}
__device__ __forceinline__ float h_lo(uint32_t p) {
    __half2 h = *(__half2*)&p; return __low2float(h);
}
__device__ __forceinline__ float h_hi(uint32_t p) {
    __half2 h = *(__half2*)&p; return __high2float(h);
}
// split (v0,v1) -> hi f16x2 and residual-lo f16x2
__device__ __forceinline__ void split2(float v0, float v1, uint32_t& hi, uint32_t& lo) {
    hi = pkh(v0, v1);
    lo = pkh(v0 - h_lo(hi), v1 - h_hi(hi));
}

__device__ __forceinline__ void mma16816(float* c,
                                         uint32_t a0, uint32_t a1, uint32_t a2, uint32_t a3,
                                         uint32_t b0, uint32_t b1) {
    asm volatile(
        "mma.sync.aligned.m16n8k16.row.col.f32.f16.f16.f32 "
        "{%0,%1,%2,%3}, {%4,%5,%6,%7}, {%8,%9}, {%0,%1,%2,%3};"
        : "+f"(c[0]), "+f"(c[1]), "+f"(c[2]), "+f"(c[3])
        : "r"(a0), "r"(a1), "r"(a2), "r"(a3), "r"(b0), "r"(b1));
}

// ---------------- Lévy noise prologue (fp64) ----------------
__global__ void noise_kernel(const float* __restrict__ u_raw,
                             const float* __restrict__ w_raw) {
    int i = blockIdx.x * blockDim.x + threadIdx.x;
    if (i >= NDEPTH * 64) return;
    double u = (double)u_raw[i];
    double w = (double)w_raw[i];
    double U = 3.14159265358979323846 * (u - 0.5);
    double wc = w; if (wc < 1e-12) wc = 1e-12; if (wc > 1.0) wc = 1.0;
    double Wv = -log(wc); if (Wv < 1e-12) Wv = 1e-12;
    const double inv_a = 1.0 / 1.8;
    double X = (sin(1.8 * U) / pow(cos(U), inv_a))
             * pow(cos(U - 1.8 * U) / Wv, (1.0 - 1.8) * inv_a);
    double n = 0.1 * X;
    if (n >  10.0) n =  10.0;
    if (n < -10.0) n = -10.0;
    g_noise[i] = (float)n;
}

// ---------------- main: 16 warps, warp w owns rows 16w..16w+15 ----------------
__global__ void __launch_bounds__(NTHREADS, 1)
sdenet_mma(const float* __restrict__ x,
           const float* __restrict__ W_down,  const float* __restrict__ b_down,
           const float* __restrict__ W_drift, const float* __restrict__ b_drift,
           const float* __restrict__ W1,      const float* __restrict__ b1,
           const float* __restrict__ W2,      const float* __restrict__ b2,
           float* __restrict__ out) {
    extern __shared__ float sm[];
    const int tid  = threadIdx.x;
    const int wid  = tid >> 5;
    const int lane = tid & 31;
    const int quad = lane >> 2;
    const int qt   = lane & 3;

    // ---- cooperative loads ----
    for (int i = tid; i < 4096; i += NTHREADS) {
        sm[F_WDOWN  + i] = W_down[i];
        sm[F_WDRIFT + i] = W_drift[i];
    }
    for (int i = tid; i < 64 * 104; i += NTHREADS) {
        int k = i / 104, n = i % 104;
        sm[F_W1 + i] = (n < 100) ? W1[k * 100 + n] : 0.0f;
    }
    for (int i = tid; i < NDEPTH * 64; i += NTHREADS) sm[F_NOISE + i] = g_noise[i];
    if (tid < 64)  { sm[F_BD + tid] = b_down[tid]; sm[F_BDR + tid] = b_drift[tid]; }
    if (tid < 104) {
        sm[F_B1 + tid] = (tid < 100) ? b1[tid] : 0.0f;
        sm[F_W2 + tid] = (tid < 100) ? W2[tid] : 0.0f;
    }
    if (tid == 0) sm[F_B2] = b2[0];

    // x tile -> stage (coalesced)
    const float* xb = x + (size_t)blockIdx.x * (TILE_M * 64);
    for (int i = 4 * tid; i < TILE_M * 64; i += 4 * NTHREADS) {
        float4 v = *(const float4*)(xb + i);
        int r = i >> 6, c = i & 63;
        *(float4*)&sm[F_STAGE + r * ST_PITCH + c] = v;
    }
    __syncthreads();

    // ---- W_drift B-fragment tables (warp 0 builds): hi and lo, uint2 per (g,lane) ----
    if (wid == 0) {
#pragma unroll
        for (int nt = 0; nt < 8; nt++)
#pragma unroll
            for (int kt = 0; kt < 4; kt++) {
                int n = quad + 8 * nt;
                int k = 16 * kt + 2 * qt;
                uint32_t b0h, b0l, b1h, b1l;
                split2(sm[F_WDRIFT + k * 64 + n],       sm[F_WDRIFT + (k + 1) * 64 + n], b0h, b0l);
                split2(sm[F_WDRIFT + (k + 8) * 64 + n], sm[F_WDRIFT + (k + 9) * 64 + n], b1h, b1l);
                int g = nt * 4 + kt;
                ((uint2*)&sm[F_BHI])[g * 32 + lane] = make_uint2(b0h, b1h);
                ((uint2*)&sm[F_BLO])[g * 32 + lane] = make_uint2(b0l, b1l);
            }
    }
    // drift bias per accumulator column position (constant across steps)
    float bdr0[8], bdr1[8];
#pragma unroll
    for (int nt = 0; nt < 8; nt++) {
        int c0 = 8 * nt + 2 * qt;
        bdr0[nt] = sm[F_BDR + c0];
        bdr1[nt] = sm[F_BDR + c0 + 1];
    }
    __syncthreads();   // publish B tables

    const int row0 = 16 * wid + quad;

    // ---- A fragments of x (hi/lo) ----
    uint32_t ah[16], al[16];
#pragma unroll
    for (int kt = 0; kt < 4; kt++) {
        int k0 = 16 * kt + 2 * qt;
        const float* r0p = &sm[F_STAGE + row0 * ST_PITCH];
        const float* r1p = &sm[F_STAGE + (row0 + 8) * ST_PITCH];
        split2(r0p[k0],     r0p[k0 + 1], ah[4*kt + 0], al[4*kt + 0]);
        split2(r1p[k0],     r1p[k0 + 1], ah[4*kt + 1], al[4*kt + 1]);
        split2(r0p[k0 + 8], r0p[k0 + 9], ah[4*kt + 2], al[4*kt + 2]);
        split2(r1p[k0 + 8], r1p[k0 + 9], ah[4*kt + 3], al[4*kt + 3]);
    }

    // ---- GEMM1: s = x @ W_down + b_down (3-term fp16, B built on the fly) ----
    float d[8][4];
#pragma unroll
    for (int nt = 0; nt < 8; nt++) {
        int c0 = 8 * nt + 2 * qt;
        float c[4] = { sm[F_BD + c0], sm[F_BD + c0 + 1], sm[F_BD + c0], sm[F_BD + c0 + 1] };
        int n = quad + 8 * nt;
#pragma unroll
        for (int kt = 0; kt < 4; kt++) {
            int k = 16 * kt + 2 * qt;
            uint32_t b0h, b0l, b1h, b1l;
            split2(sm[F_WDOWN + k * 64 + n],       sm[F_WDOWN + (k + 1) * 64 + n], b0h, b0l);
            split2(sm[F_WDOWN + (k + 8) * 64 + n], sm[F_WDOWN + (k + 9) * 64 + n], b1h, b1l);
            mma16816(c, ah[4*kt], ah[4*kt+1], ah[4*kt+2], ah[4*kt+3], b0h, b1h);
            mma16816(c, al[4*kt], al[4*kt+1], al[4*kt+2], al[4*kt+3], b0h, b1h);
            mma16816(c, ah[4*kt], ah[4*kt+1], ah[4*kt+2], ah[4*kt+3], b0l, b1l);
        }
        d[nt][0] = c[0]; d[nt][1] = c[1]; d[nt][2] = c[2]; d[nt][3] = c[3];
    }

    // rebuild A fragments from state (D layout == A layout)
#pragma unroll
    for (int kt = 0; kt < 4; kt++) {
        split2(d[2*kt][0],   d[2*kt][1],   ah[4*kt + 0], al[4*kt + 0]);
        split2(d[2*kt][2],   d[2*kt][3],   ah[4*kt + 1], al[4*kt + 1]);
        split2(d[2*kt+1][0], d[2*kt+1][1], ah[4*kt + 2], al[4*kt + 2]);
        split2(d[2*kt+1][2], d[2*kt+1][3], ah[4*kt + 3], al[4*kt + 3]);
    }

    // ---- diffusion MLP (3-term fp16) ----
    float p0 = 0.0f, p1 = 0.0f;
#pragma unroll
    for (int nt = 0; nt < 13; nt++) {
        float c[4] = {0.f, 0.f, 0.f, 0.f};
        int n = quad + 8 * nt;
#pragma unroll
        for (int kt = 0; kt < 4; kt++) {
            int k = 16 * kt + 2 * qt;
            uint32_t b0h, b0l, b1h, b1l;
            split2(sm[F_W1 + k * 104 + n],       sm[F_W1 + (k + 1) * 104 + n], b0h, b0l);
            split2(sm[F_W1 + (k + 8) * 104 + n], sm[F_W1 + (k + 9) * 104 + n], b1h, b1l);
            mma16816(c, ah[4*kt], ah[4*kt+1], ah[4*kt+2], ah[4*kt+3], b0h, b1h);
            mma16816(c, al[4*kt], al[4*kt+1], al[4*kt+2], al[4*kt+3], b0h, b1h);
            mma16816(c, ah[4*kt], ah[4*kt+1], ah[4*kt+2], ah[4*kt+3], b0l, b1l);
        }
        int c0 = 8 * nt + 2 * qt;
        float w20 = sm[F_W2 + c0], w21 = sm[F_W2 + c0 + 1];
        float bb0 = sm[F_B1 + c0], bb1 = sm[F_B1 + c0 + 1];
        p0 += fmaxf(c[0] + bb0, 0.f) * w20 + fmaxf(c[1] + bb1, 0.f) * w21;
        p1 += fmaxf(c[2] + bb0, 0.f) * w20 + fmaxf(c[3] + bb1, 0.f) * w21;
    }
    p0 += __shfl_xor_sync(0xffffffffu, p0, 1);
    p0 += __shfl_xor_sync(0xffffffffu, p0, 2);
    p1 += __shfl_xor_sync(0xffffffffu, p1, 1);
    p1 += __shfl_xor_sync(0xffffffffu, p1, 2);
    const float dtpow = powf(DT, 1.0f / 1.8f);
    const float b2v = sm[F_B2];
    const float scale0 = 0.5f * dtpow / (1.0f + expf(-(p0 + b2v)));
    const float scale1 = 0.5f * dtpow / (1.0f + expf(-(p1 + b2v)));

    // ---- 26 drift steps ----
    // steps 0..24: 2-term (A full split x B-hi) — drift enters scaled by dt,
    //              so B's fp16 quantization (2^-11) is dt-suppressed.
    // step 25 (drift_out): 3-term, full precision.
    const uint2* tbh = (const uint2*)&sm[F_BHI] + lane;
    const uint2* tbl = (const uint2*)&sm[F_BLO] + lane;
#pragma unroll 1
    for (int st = 0; st < 26; st++) {
#pragma unroll
        for (int nt = 0; nt < 8; nt++) {
            float c[4] = { bdr0[nt], bdr1[nt], bdr0[nt], bdr1[nt] };
#pragma unroll
            for (int kt = 0; kt < 4; kt++) {
                uint2 b = tbh[(nt * 4 + kt) * 32];
                mma16816(c, ah[4*kt], ah[4*kt+1], ah[4*kt+2], ah[4*kt+3], b.x, b.y);
                mma16816(c, al[4*kt], al[4*kt+1], al[4*kt+2], al[4*kt+3], b.x, b.y);
                if (st == NDEPTH) {
                    uint2 l = tbl[(nt * 4 + kt) * 32];
                    mma16816(c, ah[4*kt], ah[4*kt+1], ah[4*kt+2], ah[4*kt+3], l.x, l.y);
                }
            }
            int c0col = 8 * nt + 2 * qt;
            if (st < NDEPTH) {
                float2 nz = *(const float2*)&sm[F_NOISE + st * 64 + c0col];
                float r0 = fmaxf(c[0], 0.f), r1 = fmaxf(c[1], 0.f);
                float r2 = fmaxf(c[2], 0.f), r3 = fmaxf(c[3], 0.f);
                d[nt][0] = fmaf(r0 + d[nt][0], DT, d[nt][0]) + scale0 * nz.x;
                d[nt][1] = fmaf(r1 + d[nt][1], DT, d[nt][1]) + scale0 * nz.y;
                d[nt][2] = fmaf(r2 + d[nt][2], DT, d[nt][2]) + scale1 * nz.x;
                d[nt][3] = fmaf(r3 + d[nt][3], DT, d[nt][3]) + scale1 * nz.y;
            } else {
                sm[F_STAGE + row0 * ST_PITCH + c0col]           = fmaxf(c[0], 0.f) + d[nt][0];
                sm[F_STAGE + row0 * ST_PITCH + c0col + 1]       = fmaxf(c[1], 0.f) + d[nt][1];
                sm[F_STAGE + (row0 + 8) * ST_PITCH + c0col]     = fmaxf(c[2], 0.f) + d[nt][2];
                sm[F_STAGE + (row0 + 8) * ST_PITCH + c0col + 1] = fmaxf(c[3], 0.f) + d[nt][3];
            }
        }
        if (st < NDEPTH) {
#pragma unroll
            for (int kt = 0; kt < 4; kt++) {
                split2(d[2*kt][0],   d[2*kt][1],   ah[4*kt + 0], al[4*kt + 0]);
                split2(d[2*kt][2],   d[2*kt][3],   ah[4*kt + 1], al[4*kt + 1]);
                split2(d[2*kt+1][0], d[2*kt+1][1], ah[4*kt + 2], al[4*kt + 2]);
                split2(d[2*kt+1][2], d[2*kt+1][3], ah[4*kt + 3], al[4*kt + 3]);
            }
        }
    }

    // ---- write drift_out (coalesced via stage) ----
    __syncthreads();
    float* o0 = out + (size_t)blockIdx.x * (TILE_M * 64);
    for (int i = 4 * tid; i < TILE_M * 64; i += 4 * NTHREADS) {
        int r = i >> 6, c = i & 63;
        *(float4*)(o0 + i) = *(const float4*)&sm[F_STAGE + r * ST_PITCH + c];
    }
    __syncthreads();

    // ---- stage + write final state ----
#pragma unroll
    for (int nt = 0; nt < 8; nt++) {
        int c0col = 8 * nt + 2 * qt;
        sm[F_STAGE + row0 * ST_PITCH + c0col]           = d[nt][0];
        sm[F_STAGE + row0 * ST_PITCH + c0col + 1]       = d[nt][1];
        sm[F_STAGE + (row0 + 8) * ST_PITCH + c0col]     = d[nt][2];
        sm[F_STAGE + (row0 + 8) * ST_PITCH + c0col + 1] = d[nt][3];
    }
    __syncthreads();
    float* o1 = out + (size_t)NBATCH * 64 + (size_t)blockIdx.x * (TILE_M * 64);
    for (int i = 4 * tid; i < TILE_M * 64; i += 4 * NTHREADS) {
        int r = i >> 6, c = i & 63;
        *(float4*)(o1 + i) = *(const float4*)&sm[F_STAGE + r * ST_PITCH + c];
    }
}

extern "C" void kernel_launch(void* const* d_in, const int* in_sizes, int n_in,
                              void* d_out, int out_size) {
    const float* x       = (const float*)d_in[0];
    const float* u_raw   = (const float*)d_in[1];
    const float* w_raw   = (const float*)d_in[2];
    const float* W_down  = (const float*)d_in[3];
    const float* b_down  = (const float*)d_in[4];
    const float* W_drift = (const float*)d_in[5];
    const float* b_drift = (const float*)d_in[6];
    const float* W1      = (const float*)d_in[7];
    const float* b1      = (const float*)d_in[8];
    const float* W2      = (const float*)d_in[9];
    const float* b2      = (const float*)d_in[10];
    float* out = (float*)d_out;

    noise_kernel<<<(NDEPTH * 64 + 255) / 256, 256>>>(u_raw, w_raw);

    cudaFuncSetAttribute(sdenet_mma,
                         cudaFuncAttributeMaxDynamicSharedMemorySize, SMEM_BYTES);
    sdenet_mma<<<NBATCH / TILE_M, NTHREADS, SMEM_BYTES>>>(
        x, W_down, b_down, W_drift, b_drift, W1, b1, W2, b2, out);
}

// round 6
// speedup vs baseline: 4.1280x; 1.2130x over previous
#include <cuda_runtime.h>
#include <cuda_fp16.h>
#include <math.h>
#include <stdint.h>

#define NDEPTH 25
#define DT     (1.0f/25.0f)
#define NBATCH 262144
#define TILE_M 256
#define NTHREADS 512

// ---------------- smem float-index offsets ----------------
#define F_WDOWN  0            // 64x64
#define F_WDRIFT 4096         // 64x64
#define F_W1     8192         // 64x104 (padded)
#define F_NOISE  14848        // 25x64
#define F_BD     16448        // 64
#define F_BDR    16512        // 64
#define F_B1     16576        // 104
#define F_W2     16680        // 104
#define F_B2     16784        // 1 (pad 4)
#define F_B4     16788        // 32 groups x 32 lanes x uint4 {b0h,b1h,b0l,b1l} (16KB)
#define F_STAGE  20884        // 256 rows x pitch 68
#define ST_PITCH 68
#define F_TOTAL  (F_STAGE + 256*ST_PITCH)
#define SMEM_BYTES (F_TOTAL*4)        // 153168 B

__device__ float g_noise[NDEPTH*64];

// ---------------- fp16 pack/split helpers ----------------
__device__ __forceinline__ uint32_t pkh(float e0, float e1) {
    uint32_t r;
    asm("cvt.rn.f16x2.f32 %0, %1, %2;" : "=r"(r) : "f"(e1), "f"(e0));
    return r;
}
__device__ __forceinline__ float h_lo(uint32_t p) {
    __half2 h = *(__half2*)&p; return __low2float(h);
}
__device__ __forceinline__ float h_hi(uint32_t p) {
    __half2 h = *(__half2*)&p; return __high2float(h);
}
__device__ __forceinline__ void split2(float v0, float v1, uint32_t& hi, uint32_t& lo) {
    hi = pkh(v0, v1);
    lo = pkh(v0 - h_lo(hi), v1 - h_hi(hi));
}

__device__ __forceinline__ void mma16816(float* c,
                                         uint32_t a0, uint32_t a1, uint32_t a2, uint32_t a3,
                                         uint32_t b0, uint32_t b1) {
    asm volatile(
        "mma.sync.aligned.m16n8k16.row.col.f32.f16.f16.f32 "
        "{%0,%1,%2,%3}, {%4,%5,%6,%7}, {%8,%9}, {%0,%1,%2,%3};"
        : "+f"(c[0]), "+f"(c[1]), "+f"(c[2]), "+f"(c[3])
        : "r"(a0), "r"(a1), "r"(a2), "r"(a3), "r"(b0), "r"(b1));
}

// ---------------- Lévy noise prologue (fp64) ----------------
__global__ void noise_kernel(const float* __restrict__ u_raw,
                             const float* __restrict__ w_raw) {
    int i = blockIdx.x * blockDim.x + threadIdx.x;
    if (i >= NDEPTH * 64) return;
    double u = (double)u_raw[i];
    double w = (double)w_raw[i];
    double U = 3.14159265358979323846 * (u - 0.5);
    double wc = w; if (wc < 1e-12) wc = 1e-12; if (wc > 1.0) wc = 1.0;
    double Wv = -log(wc); if (Wv < 1e-12) Wv = 1e-12;
    const double inv_a = 1.0 / 1.8;
    double X = (sin(1.8 * U) / pow(cos(U), inv_a))
             * pow(cos(U - 1.8 * U) / Wv, (1.0 - 1.8) * inv_a);
    double n = 0.1 * X;
    if (n >  10.0) n =  10.0;
    if (n < -10.0) n = -10.0;
    g_noise[i] = (float)n;
}

// ---------------- main: 16 warps, warp w owns rows 16w..16w+15 ----------------
__global__ void __launch_bounds__(NTHREADS, 1)
sdenet_mma(const float* __restrict__ x,
           const float* __restrict__ W_down,  const float* __restrict__ b_down,
           const float* __restrict__ W_drift, const float* __restrict__ b_drift,
           const float* __restrict__ W1,      const float* __restrict__ b1,
           const float* __restrict__ W2,      const float* __restrict__ b2,
           float* __restrict__ out) {
    extern __shared__ float sm[];
    const int tid  = threadIdx.x;
    const int wid  = tid >> 5;
    const int lane = tid & 31;
    const int quad = lane >> 2;
    const int qt   = lane & 3;

    // ---- cooperative loads ----
    for (int i = tid; i < 4096; i += NTHREADS) {
        sm[F_WDOWN  + i] = W_down[i];
        sm[F_WDRIFT + i] = W_drift[i];
    }
    for (int i = tid; i < 64 * 104; i += NTHREADS) {
        int k = i / 104, n = i % 104;
        sm[F_W1 + i] = (n < 100) ? W1[k * 100 + n] : 0.0f;
    }
    for (int i = tid; i < NDEPTH * 64; i += NTHREADS) sm[F_NOISE + i] = g_noise[i];
    if (tid < 64)  { sm[F_BD + tid] = b_down[tid]; sm[F_BDR + tid] = b_drift[tid]; }
    if (tid < 104) {
        sm[F_B1 + tid] = (tid < 100) ? b1[tid] : 0.0f;
        sm[F_W2 + tid] = (tid < 100) ? W2[tid] : 0.0f;
    }
    if (tid == 0) sm[F_B2] = b2[0];

    // x tile -> stage (coalesced)
    const float* xb = x + (size_t)blockIdx.x * (TILE_M * 64);
    for (int i = 4 * tid; i < TILE_M * 64; i += 4 * NTHREADS) {
        float4 v = *(const float4*)(xb + i);
        int r = i >> 6, c = i & 63;
        *(float4*)&sm[F_STAGE + r * ST_PITCH + c] = v;
    }
    __syncthreads();

    // ---- W_drift B-fragment table (warp 0 builds): uint4 {b0h,b1h,b0l,b1l} per (g,lane) ----
    if (wid == 0) {
#pragma unroll
        for (int nt = 0; nt < 8; nt++)
#pragma unroll
            for (int kt = 0; kt < 4; kt++) {
                int n = quad + 8 * nt;
                int k = 16 * kt + 2 * qt;
                uint32_t b0h, b0l, b1h, b1l;
                split2(sm[F_WDRIFT + k * 64 + n],       sm[F_WDRIFT + (k + 1) * 64 + n], b0h, b0l);
                split2(sm[F_WDRIFT + (k + 8) * 64 + n], sm[F_WDRIFT + (k + 9) * 64 + n], b1h, b1l);
                int g = nt * 4 + kt;
                ((uint4*)&sm[F_B4])[g * 32 + lane] = make_uint4(b0h, b1h, b0l, b1l);
            }
    }
    // drift bias per accumulator column position (constant across steps)
    float bdr0[8], bdr1[8];
#pragma unroll
    for (int nt = 0; nt < 8; nt++) {
        int c0 = 8 * nt + 2 * qt;
        bdr0[nt] = sm[F_BDR + c0];
        bdr1[nt] = sm[F_BDR + c0 + 1];
    }
    __syncthreads();   // publish B table

    const int row0 = 16 * wid + quad;

    // ---- A fragments of x (hi/lo) ----
    uint32_t ah[16], al[16];
#pragma unroll
    for (int kt = 0; kt < 4; kt++) {
        int k0 = 16 * kt + 2 * qt;
        const float* r0p = &sm[F_STAGE + row0 * ST_PITCH];
        const float* r1p = &sm[F_STAGE + (row0 + 8) * ST_PITCH];
        split2(r0p[k0],     r0p[k0 + 1], ah[4*kt + 0], al[4*kt + 0]);
        split2(r1p[k0],     r1p[k0 + 1], ah[4*kt + 1], al[4*kt + 1]);
        split2(r0p[k0 + 8], r0p[k0 + 9], ah[4*kt + 2], al[4*kt + 2]);
        split2(r1p[k0 + 8], r1p[k0 + 9], ah[4*kt + 3], al[4*kt + 3]);
    }

    // ---- GEMM1: s = x @ W_down + b_down (3-term fp16, B built on the fly) ----
    float d[8][4];
#pragma unroll
    for (int nt = 0; nt < 8; nt++) {
        int c0 = 8 * nt + 2 * qt;
        float c[4] = { sm[F_BD + c0], sm[F_BD + c0 + 1], sm[F_BD + c0], sm[F_BD + c0 + 1] };
        int n = quad + 8 * nt;
#pragma unroll
        for (int kt = 0; kt < 4; kt++) {
            int k = 16 * kt + 2 * qt;
            uint32_t b0h, b0l, b1h, b1l;
            split2(sm[F_WDOWN + k * 64 + n],       sm[F_WDOWN + (k + 1) * 64 + n], b0h, b0l);
            split2(sm[F_WDOWN + (k + 8) * 64 + n], sm[F_WDOWN + (k + 9) * 64 + n], b1h, b1l);
            mma16816(c, ah[4*kt], ah[4*kt+1], ah[4*kt+2], ah[4*kt+3], b0h, b1h);
            mma16816(c, al[4*kt], al[4*kt+1], al[4*kt+2], al[4*kt+3], b0h, b1h);
            mma16816(c, ah[4*kt], ah[4*kt+1], ah[4*kt+2], ah[4*kt+3], b0l, b1l);
        }
        d[nt][0] = c[0]; d[nt][1] = c[1]; d[nt][2] = c[2]; d[nt][3] = c[3];
    }

    // rebuild A fragments from state (full split for MLP precision)
#pragma unroll
    for (int kt = 0; kt < 4; kt++) {
        split2(d[2*kt][0],   d[2*kt][1],   ah[4*kt + 0], al[4*kt + 0]);
        split2(d[2*kt][2],   d[2*kt][3],   ah[4*kt + 1], al[4*kt + 1]);
        split2(d[2*kt+1][0], d[2*kt+1][1], ah[4*kt + 2], al[4*kt + 2]);
        split2(d[2*kt+1][2], d[2*kt+1][3], ah[4*kt + 3], al[4*kt + 3]);
    }

    // ---- diffusion MLP (3-term fp16) ----
    float p0 = 0.0f, p1 = 0.0f;
#pragma unroll
    for (int nt = 0; nt < 13; nt++) {
        float c[4] = {0.f, 0.f, 0.f, 0.f};
        int n = quad + 8 * nt;
#pragma unroll
        for (int kt = 0; kt < 4; kt++) {
            int k = 16 * kt + 2 * qt;
            uint32_t b0h, b0l, b1h, b1l;
            split2(sm[F_W1 + k * 104 + n],       sm[F_W1 + (k + 1) * 104 + n], b0h, b0l);
            split2(sm[F_W1 + (k + 8) * 104 + n], sm[F_W1 + (k + 9) * 104 + n], b1h, b1l);
            mma16816(c, ah[4*kt], ah[4*kt+1], ah[4*kt+2], ah[4*kt+3], b0h, b1h);
            mma16816(c, al[4*kt], al[4*kt+1], al[4*kt+2], al[4*kt+3], b0h, b1h);
            mma16816(c, ah[4*kt], ah[4*kt+1], ah[4*kt+2], ah[4*kt+3], b0l, b1l);
        }
        int c0 = 8 * nt + 2 * qt;
        float w20 = sm[F_W2 + c0], w21 = sm[F_W2 + c0 + 1];
        float bb0 = sm[F_B1 + c0], bb1 = sm[F_B1 + c0 + 1];
        p0 += fmaxf(c[0] + bb0, 0.f) * w20 + fmaxf(c[1] + bb1, 0.f) * w21;
        p1 += fmaxf(c[2] + bb0, 0.f) * w20 + fmaxf(c[3] + bb1, 0.f) * w21;
    }
    p0 += __shfl_xor_sync(0xffffffffu, p0, 1);
    p0 += __shfl_xor_sync(0xffffffffu, p0, 2);
    p1 += __shfl_xor_sync(0xffffffffu, p1, 1);
    p1 += __shfl_xor_sync(0xffffffffu, p1, 2);
    const float dtpow = powf(DT, 1.0f / 1.8f);
    const float b2v = sm[F_B2];
    const float scale0 = 0.5f * dtpow / (1.0f + expf(-(p0 + b2v)));
    const float scale1 = 0.5f * dtpow / (1.0f + expf(-(p1 + b2v)));

    // ---- 25 drift steps: A-hi only x full-split B (2 MMAs per frag) ----
    // Residual precision rides on B (step-invariant, in smem); the A rebuild
    // is a bare cvt per fragment instead of a full split.
    const uint4* tb4 = (const uint4*)&sm[F_B4] + lane;
#pragma unroll 1
    for (int st = 0; st < NDEPTH; st++) {
#pragma unroll
        for (int nt = 0; nt < 8; nt++) {
            float c[4] = { bdr0[nt], bdr1[nt], bdr0[nt], bdr1[nt] };
#pragma unroll
            for (int kt = 0; kt < 4; kt++) {
                uint4 b = tb4[(nt * 4 + kt) * 32];
                mma16816(c, ah[4*kt], ah[4*kt+1], ah[4*kt+2], ah[4*kt+3], b.x, b.y);
                mma16816(c, ah[4*kt], ah[4*kt+1], ah[4*kt+2], ah[4*kt+3], b.z, b.w);
            }
            int c0col = 8 * nt + 2 * qt;
            float2 nz = *(const float2*)&sm[F_NOISE + st * 64 + c0col];
            float r0 = fmaxf(c[0], 0.f), r1 = fmaxf(c[1], 0.f);
            float r2 = fmaxf(c[2], 0.f), r3 = fmaxf(c[3], 0.f);
            d[nt][0] = fmaf(r0 + d[nt][0], DT, d[nt][0]) + scale0 * nz.x;
            d[nt][1] = fmaf(r1 + d[nt][1], DT, d[nt][1]) + scale0 * nz.y;
            d[nt][2] = fmaf(r2 + d[nt][2], DT, d[nt][2]) + scale1 * nz.x;
            d[nt][3] = fmaf(r3 + d[nt][3], DT, d[nt][3]) + scale1 * nz.y;
        }
        // A-hi rebuild: one cvt per fragment
#pragma unroll
        for (int kt = 0; kt < 4; kt++) {
            ah[4*kt + 0] = pkh(d[2*kt][0],   d[2*kt][1]);
            ah[4*kt + 1] = pkh(d[2*kt][2],   d[2*kt][3]);
            ah[4*kt + 2] = pkh(d[2*kt+1][0], d[2*kt+1][1]);
            ah[4*kt + 3] = pkh(d[2*kt+1][2], d[2*kt+1][3]);
        }
    }

    // ---- final drift_out GEMM: full precision (3-term, A fully split) ----
#pragma unroll
    for (int kt = 0; kt < 4; kt++) {
        split2(d[2*kt][0],   d[2*kt][1],   ah[4*kt + 0], al[4*kt + 0]);
        split2(d[2*kt][2],   d[2*kt][3],   ah[4*kt + 1], al[4*kt + 1]);
        split2(d[2*kt+1][0], d[2*kt+1][1], ah[4*kt + 2], al[4*kt + 2]);
        split2(d[2*kt+1][2], d[2*kt+1][3], ah[4*kt + 3], al[4*kt + 3]);
    }
#pragma unroll
    for (int nt = 0; nt < 8; nt++) {
        float c[4] = { bdr0[nt], bdr1[nt], bdr0[nt], bdr1[nt] };
#pragma unroll
        for (int kt = 0; kt < 4; kt++) {
            uint4 b = tb4[(nt * 4 + kt) * 32];
            mma16816(c, ah[4*kt], ah[4*kt+1], ah[4*kt+2], ah[4*kt+3], b.x, b.y);
            mma16816(c, al[4*kt], al[4*kt+1], al[4*kt+2], al[4*kt+3], b.x, b.y);
            mma16816(c, ah[4*kt], ah[4*kt+1], ah[4*kt+2], ah[4*kt+3], b.z, b.w);
        }
        int c0col = 8 * nt + 2 * qt;
        sm[F_STAGE + row0 * ST_PITCH + c0col]           = fmaxf(c[0], 0.f) + d[nt][0];
        sm[F_STAGE + row0 * ST_PITCH + c0col + 1]       = fmaxf(c[1], 0.f) + d[nt][1];
        sm[F_STAGE + (row0 + 8) * ST_PITCH + c0col]     = fmaxf(c[2], 0.f) + d[nt][2];
        sm[F_STAGE + (row0 + 8) * ST_PITCH + c0col + 1] = fmaxf(c[3], 0.f) + d[nt][3];
    }

    // ---- write drift_out (coalesced via stage) ----
    __syncthreads();
    float* o0 = out + (size_t)blockIdx.x * (TILE_M * 64);
    for (int i = 4 * tid; i < TILE_M * 64; i += 4 * NTHREADS) {
        int r = i >> 6, c = i & 63;
        *(float4*)(o0 + i) = *(const float4*)&sm[F_STAGE + r * ST_PITCH + c];
    }
    __syncthreads();

    // ---- stage + write final state ----
#pragma unroll
    for (int nt = 0; nt < 8; nt++) {
        int c0col = 8 * nt + 2 * qt;
        sm[F_STAGE + row0 * ST_PITCH + c0col]           = d[nt][0];
        sm[F_STAGE + row0 * ST_PITCH + c0col + 1]       = d[nt][1];
        sm[F_STAGE + (row0 + 8) * ST_PITCH + c0col]     = d[nt][2];
        sm[F_STAGE + (row0 + 8) * ST_PITCH + c0col + 1] = d[nt][3];
    }
    __syncthreads();
    float* o1 = out + (size_t)NBATCH * 64 + (size_t)blockIdx.x * (TILE_M * 64);
    for (int i = 4 * tid; i < TILE_M * 64; i += 4 * NTHREADS) {
        int r = i >> 6, c = i & 63;
        *(float4*)(o1 + i) = *(const float4*)&sm[F_STAGE + r * ST_PITCH + c];
    }
}

extern "C" void kernel_launch(void* const* d_in, const int* in_sizes, int n_in,
                              void* d_out, int out_size) {
    const float* x       = (const float*)d_in[0];
    const float* u_raw   = (const float*)d_in[1];
    const float* w_raw   = (const float*)d_in[2];
    const float* W_down  = (const float*)d_in[3];
    const float* b_down  = (const float*)d_in[4];
    const float* W_drift = (const float*)d_in[5];
    const float* b_drift = (const float*)d_in[6];
    const float* W1      = (const float*)d_in[7];
    const float* b1      = (const float*)d_in[8];
    const float* W2      = (const float*)d_in[9];
    const float* b2      = (const float*)d_in[10];
    float* out = (float*)d_out;

    noise_kernel<<<(NDEPTH * 64 + 255) / 256, 256>>>(u_raw, w_raw);

    cudaFuncSetAttribute(sdenet_mma,
                         cudaFuncAttributeMaxDynamicSharedMemorySize, SMEM_BYTES);
    sdenet_mma<<<NBATCH / TILE_M, NTHREADS, SMEM_BYTES>>>(
        x, W_down, b_down, W_drift, b_drift, W1, b1, W2, b2, out);
}

// round 7
// speedup vs baseline: 5.3341x; 1.2922x over previous
#include <cuda_runtime.h>
#include <cuda_fp16.h>
#include <math.h>
#include <stdint.h>

#define NDEPTH 25
#define DT     (1.0f/25.0f)
#define NBATCH 262144
#define TILE_M 256
#define NTHREADS 512

// ---------------- smem float-index offsets ----------------
#define F_WDOWN  0            // 64x64
#define F_WDRIFT 4096         // 64x64
#define F_W1     8192         // 64x104 (padded)
#define F_NOISE  14848        // 25x64
#define F_BD     16448        // 64
#define F_BDR    16512        // 64
#define F_B1     16576        // 104
#define F_W2     16680        // 104
#define F_B2     16784        // 1 (pad 4)
#define F_BHI    16788        // 32 groups x 32 lanes x uint2 (hi frags, 8KB)
#define F_BLO    18836        // 32 groups x 32 lanes x uint2 (lo frags, 8KB)
#define F_STAGE  20884        // 256 rows x pitch 68
#define ST_PITCH 68
#define F_TOTAL  (F_STAGE + 256*ST_PITCH)
#define SMEM_BYTES (F_TOTAL*4)        // 153168 B

__device__ float g_noise[NDEPTH*64];

// ---------------- fp16 pack/split helpers ----------------
__device__ __forceinline__ uint32_t pkh(float e0, float e1) {
    uint32_t r;
    asm("cvt.rn.f16x2.f32 %0, %1, %2;" : "=r"(r) : "f"(e1), "f"(e0));
    return r;
}
__device__ __forceinline__ float h_lo(uint32_t p) {
    __half2 h = *(__half2*)&p; return __low2float(h);
}
__device__ __forceinline__ float h_hi(uint32_t p) {
    __half2 h = *(__half2*)&p; return __high2float(h);
}
__device__ __forceinline__ void split2(float v0, float v1, uint32_t& hi, uint32_t& lo) {
    hi = pkh(v0, v1);
    lo = pkh(v0 - h_lo(hi), v1 - h_hi(hi));
}

__device__ __forceinline__ void mma16816(float* c,
                                         uint32_t a0, uint32_t a1, uint32_t a2, uint32_t a3,
                                         uint32_t b0, uint32_t b1) {
    asm volatile(
        "mma.sync.aligned.m16n8k16.row.col.f32.f16.f16.f32 "
        "{%0,%1,%2,%3}, {%4,%5,%6,%7}, {%8,%9}, {%0,%1,%2,%3};"
        : "+f"(c[0]), "+f"(c[1]), "+f"(c[2]), "+f"(c[3])
        : "r"(a0), "r"(a1), "r"(a2), "r"(a3), "r"(b0), "r"(b1));
}

// ---------------- Lévy noise prologue (fp64) ----------------
__global__ void noise_kernel(const float* __restrict__ u_raw,
                             const float* __restrict__ w_raw) {
    int i = blockIdx.x * blockDim.x + threadIdx.x;
    if (i >= NDEPTH * 64) return;
    double u = (double)u_raw[i];
    double w = (double)w_raw[i];
    double U = 3.14159265358979323846 * (u - 0.5);
    double wc = w; if (wc < 1e-12) wc = 1e-12; if (wc > 1.0) wc = 1.0;
    double Wv = -log(wc); if (Wv < 1e-12) Wv = 1e-12;
    const double inv_a = 1.0 / 1.8;
    double X = (sin(1.8 * U) / pow(cos(U), inv_a))
             * pow(cos(U - 1.8 * U) / Wv, (1.0 - 1.8) * inv_a);
    double n = 0.1 * X;
    if (n >  10.0) n =  10.0;
    if (n < -10.0) n = -10.0;
    g_noise[i] = (float)n;
}

// ---------------- main: 16 warps, warp w owns rows 16w..16w+15 ----------------
__global__ void __launch_bounds__(NTHREADS, 1)
sdenet_mma(const float* __restrict__ x,
           const float* __restrict__ W_down,  const float* __restrict__ b_down,
           const float* __restrict__ W_drift, const float* __restrict__ b_drift,
           const float* __restrict__ W1,      const float* __restrict__ b1,
           const float* __restrict__ W2,      const float* __restrict__ b2,
           float* __restrict__ out) {
    extern __shared__ float sm[];
    const int tid  = threadIdx.x;
    const int wid  = tid >> 5;
    const int lane = tid & 31;
    const int quad = lane >> 2;
    const int qt   = lane & 3;

    // ---- cooperative loads ----
    for (int i = tid; i < 4096; i += NTHREADS) {
        sm[F_WDOWN  + i] = W_down[i];
        sm[F_WDRIFT + i] = W_drift[i];
    }
    for (int i = tid; i < 64 * 104; i += NTHREADS) {
        int k = i / 104, n = i % 104;
        sm[F_W1 + i] = (n < 100) ? W1[k * 100 + n] : 0.0f;
    }
    for (int i = tid; i < NDEPTH * 64; i += NTHREADS) sm[F_NOISE + i] = g_noise[i];
    if (tid < 64)  { sm[F_BD + tid] = b_down[tid]; sm[F_BDR + tid] = b_drift[tid]; }
    if (tid < 104) {
        sm[F_B1 + tid] = (tid < 100) ? b1[tid] : 0.0f;
        sm[F_W2 + tid] = (tid < 100) ? W2[tid] : 0.0f;
    }
    if (tid == 0) sm[F_B2] = b2[0];

    // x tile -> stage (coalesced)
    const float* xb = x + (size_t)blockIdx.x * (TILE_M * 64);
    for (int i = 4 * tid; i < TILE_M * 64; i += 4 * NTHREADS) {
        float4 v = *(const float4*)(xb + i);
        int r = i >> 6, c = i & 63;
        *(float4*)&sm[F_STAGE + r * ST_PITCH + c] = v;
    }
    __syncthreads();

    // ---- W_drift B-fragment tables (warp 0 builds): hi / lo, uint2 per (g,lane) ----
    if (wid == 0) {
#pragma unroll
        for (int nt = 0; nt < 8; nt++)
#pragma unroll
            for (int kt = 0; kt < 4; kt++) {
                int n = quad + 8 * nt;
                int k = 16 * kt + 2 * qt;
                uint32_t b0h, b0l, b1h, b1l;
                split2(sm[F_WDRIFT + k * 64 + n],       sm[F_WDRIFT + (k + 1) * 64 + n], b0h, b0l);
                split2(sm[F_WDRIFT + (k + 8) * 64 + n], sm[F_WDRIFT + (k + 9) * 64 + n], b1h, b1l);
                int g = nt * 4 + kt;
                ((uint2*)&sm[F_BHI])[g * 32 + lane] = make_uint2(b0h, b1h);
                ((uint2*)&sm[F_BLO])[g * 32 + lane] = make_uint2(b0l, b1l);
            }
    }
    // drift bias per accumulator column position (constant across steps)
    float bdr0[8], bdr1[8];
#pragma unroll
    for (int nt = 0; nt < 8; nt++) {
        int c0 = 8 * nt + 2 * qt;
        bdr0[nt] = sm[F_BDR + c0];
        bdr1[nt] = sm[F_BDR + c0 + 1];
    }
    __syncthreads();   // publish B tables

    const int row0 = 16 * wid + quad;

    // ---- A fragments of x (hi/lo) ----
    uint32_t ah[16], al[16];
#pragma unroll
    for (int kt = 0; kt < 4; kt++) {
        int k0 = 16 * kt + 2 * qt;
        const float* r0p = &sm[F_STAGE + row0 * ST_PITCH];
        const float* r1p = &sm[F_STAGE + (row0 + 8) * ST_PITCH];
        split2(r0p[k0],     r0p[k0 + 1], ah[4*kt + 0], al[4*kt + 0]);
        split2(r1p[k0],     r1p[k0 + 1], ah[4*kt + 1], al[4*kt + 1]);
        split2(r0p[k0 + 8], r0p[k0 + 9], ah[4*kt + 2], al[4*kt + 2]);
        split2(r1p[k0 + 8], r1p[k0 + 9], ah[4*kt + 3], al[4*kt + 3]);
    }

    // ---- GEMM1: s = x @ W_down + b_down (3-term fp16, B built on the fly) ----
    float d[8][4];
#pragma unroll
    for (int nt = 0; nt < 8; nt++) {
        int c0 = 8 * nt + 2 * qt;
        float c[4] = { sm[F_BD + c0], sm[F_BD + c0 + 1], sm[F_BD + c0], sm[F_BD + c0 + 1] };
        int n = quad + 8 * nt;
#pragma unroll
        for (int kt = 0; kt < 4; kt++) {
            int k = 16 * kt + 2 * qt;
            uint32_t b0h, b0l, b1h, b1l;
            split2(sm[F_WDOWN + k * 64 + n],       sm[F_WDOWN + (k + 1) * 64 + n], b0h, b0l);
            split2(sm[F_WDOWN + (k + 8) * 64 + n], sm[F_WDOWN + (k + 9) * 64 + n], b1h, b1l);
            mma16816(c, ah[4*kt], ah[4*kt+1], ah[4*kt+2], ah[4*kt+3], b0h, b1h);
            mma16816(c, al[4*kt], al[4*kt+1], al[4*kt+2], al[4*kt+3], b0h, b1h);
            mma16816(c, ah[4*kt], ah[4*kt+1], ah[4*kt+2], ah[4*kt+3], b0l, b1l);
        }
        d[nt][0] = c[0]; d[nt][1] = c[1]; d[nt][2] = c[2]; d[nt][3] = c[3];
    }

    // rebuild A fragments from state (full split for MLP precision)
#pragma unroll
    for (int kt = 0; kt < 4; kt++) {
        split2(d[2*kt][0],   d[2*kt][1],   ah[4*kt + 0], al[4*kt + 0]);
        split2(d[2*kt][2],   d[2*kt][3],   ah[4*kt + 1], al[4*kt + 1]);
        split2(d[2*kt+1][0], d[2*kt+1][1], ah[4*kt + 2], al[4*kt + 2]);
        split2(d[2*kt+1][2], d[2*kt+1][3], ah[4*kt + 3], al[4*kt + 3]);
    }

    // ---- diffusion MLP (3-term fp16) ----
    float p0 = 0.0f, p1 = 0.0f;
#pragma unroll
    for (int nt = 0; nt < 13; nt++) {
        float c[4] = {0.f, 0.f, 0.f, 0.f};
        int n = quad + 8 * nt;
#pragma unroll
        for (int kt = 0; kt < 4; kt++) {
            int k = 16 * kt + 2 * qt;
            uint32_t b0h, b0l, b1h, b1l;
            split2(sm[F_W1 + k * 104 + n],       sm[F_W1 + (k + 1) * 104 + n], b0h, b0l);
            split2(sm[F_W1 + (k + 8) * 104 + n], sm[F_W1 + (k + 9) * 104 + n], b1h, b1l);
            mma16816(c, ah[4*kt], ah[4*kt+1], ah[4*kt+2], ah[4*kt+3], b0h, b1h);
            mma16816(c, al[4*kt], al[4*kt+1], al[4*kt+2], al[4*kt+3], b0h, b1h);
            mma16816(c, ah[4*kt], ah[4*kt+1], ah[4*kt+2], ah[4*kt+3], b0l, b1l);
        }
        int c0 = 8 * nt + 2 * qt;
        float w20 = sm[F_W2 + c0], w21 = sm[F_W2 + c0 + 1];
        float bb0 = sm[F_B1 + c0], bb1 = sm[F_B1 + c0 + 1];
        p0 += fmaxf(c[0] + bb0, 0.f) * w20 + fmaxf(c[1] + bb1, 0.f) * w21;
        p1 += fmaxf(c[2] + bb0, 0.f) * w20 + fmaxf(c[3] + bb1, 0.f) * w21;
    }
    p0 += __shfl_xor_sync(0xffffffffu, p0, 1);
    p0 += __shfl_xor_sync(0xffffffffu, p0, 2);
    p1 += __shfl_xor_sync(0xffffffffu, p1, 1);
    p1 += __shfl_xor_sync(0xffffffffu, p1, 2);
    const float dtpow = powf(DT, 1.0f / 1.8f);
    const float b2v = sm[F_B2];
    const float scale0 = 0.5f * dtpow / (1.0f + expf(-(p0 + b2v)));
    const float scale1 = 0.5f * dtpow / (1.0f + expf(-(p1 + b2v)));

    // ---- 25 drift steps: SINGLE-term A-hi x B-hi (1 MMA per frag) ----
    // Error budget: A-quant (damped, ~2.6e-5) + B-quant (systematic, ~1.2e-4)
    // both well under 1e-3. LDS halves to LDS.64, HMMA halves.
    const uint2* tbh = (const uint2*)&sm[F_BHI] + lane;
    const uint2* tbl = (const uint2*)&sm[F_BLO] + lane;
#pragma unroll 1
    for (int st = 0; st < NDEPTH; st++) {
#pragma unroll
        for (int nt = 0; nt < 8; nt++) {
            float c[4] = { bdr0[nt], bdr1[nt], bdr0[nt], bdr1[nt] };
#pragma unroll
            for (int kt = 0; kt < 4; kt++) {
                uint2 b = tbh[(nt * 4 + kt) * 32];
                mma16816(c, ah[4*kt], ah[4*kt+1], ah[4*kt+2], ah[4*kt+3], b.x, b.y);
            }
            int c0col = 8 * nt + 2 * qt;
            float2 nz = *(const float2*)&sm[F_NOISE + st * 64 + c0col];
            float r0 = fmaxf(c[0], 0.f), r1 = fmaxf(c[1], 0.f);
            float r2 = fmaxf(c[2], 0.f), r3 = fmaxf(c[3], 0.f);
            d[nt][0] = fmaf(r0 + d[nt][0], DT, d[nt][0]) + scale0 * nz.x;
            d[nt][1] = fmaf(r1 + d[nt][1], DT, d[nt][1]) + scale0 * nz.y;
            d[nt][2] = fmaf(r2 + d[nt][2], DT, d[nt][2]) + scale1 * nz.x;
            d[nt][3] = fmaf(r3 + d[nt][3], DT, d[nt][3]) + scale1 * nz.y;
        }
        // A-hi rebuild: one cvt per fragment
#pragma unroll
        for (int kt = 0; kt < 4; kt++) {
            ah[4*kt + 0] = pkh(d[2*kt][0],   d[2*kt][1]);
            ah[4*kt + 1] = pkh(d[2*kt][2],   d[2*kt][3]);
            ah[4*kt + 2] = pkh(d[2*kt+1][0], d[2*kt+1][1]);
            ah[4*kt + 3] = pkh(d[2*kt+1][2], d[2*kt+1][3]);
        }
    }

    // ---- final drift_out GEMM: full precision (3-term, A fully split) ----
#pragma unroll
    for (int kt = 0; kt < 4; kt++) {
        split2(d[2*kt][0],   d[2*kt][1],   ah[4*kt + 0], al[4*kt + 0]);
        split2(d[2*kt][2],   d[2*kt][3],   ah[4*kt + 1], al[4*kt + 1]);
        split2(d[2*kt+1][0], d[2*kt+1][1], ah[4*kt + 2], al[4*kt + 2]);
        split2(d[2*kt+1][2], d[2*kt+1][3], ah[4*kt + 3], al[4*kt + 3]);
    }
#pragma unroll
    for (int nt = 0; nt < 8; nt++) {
        float c[4] = { bdr0[nt], bdr1[nt], bdr0[nt], bdr1[nt] };
#pragma unroll
        for (int kt = 0; kt < 4; kt++) {
            uint2 b = tbh[(nt * 4 + kt) * 32];
            uint2 l = tbl[(nt * 4 + kt) * 32];
            mma16816(c, ah[4*kt], ah[4*kt+1], ah[4*kt+2], ah[4*kt+3], b.x, b.y);
            mma16816(c, al[4*kt], al[4*kt+1], al[4*kt+2], al[4*kt+3], b.x, b.y);
            mma16816(c, ah[4*kt], ah[4*kt+1], ah[4*kt+2], ah[4*kt+3], l.x, l.y);
        }
        int c0col = 8 * nt + 2 * qt;
        sm[F_STAGE + row0 * ST_PITCH + c0col]           = fmaxf(c[0], 0.f) + d[nt][0];
        sm[F_STAGE + row0 * ST_PITCH + c0col + 1]       = fmaxf(c[1], 0.f) + d[nt][1];
        sm[F_STAGE + (row0 + 8) * ST_PITCH + c0col]     = fmaxf(c[2], 0.f) + d[nt][2];
        sm[F_STAGE + (row0 + 8) * ST_PITCH + c0col + 1] = fmaxf(c[3], 0.f) + d[nt][3];
    }

    // ---- write drift_out (coalesced via stage) ----
    __syncthreads();
    float* o0 = out + (size_t)blockIdx.x * (TILE_M * 64);
    for (int i = 4 * tid; i < TILE_M * 64; i += 4 * NTHREADS) {
        int r = i >> 6, c = i & 63;
        *(float4*)(o0 + i) = *(const float4*)&sm[F_STAGE + r * ST_PITCH + c];
    }
    __syncthreads();

    // ---- stage + write final state ----
#pragma unroll
    for (int nt = 0; nt < 8; nt++) {
        int c0col = 8 * nt + 2 * qt;
        sm[F_STAGE + row0 * ST_PITCH + c0col]           = d[nt][0];
        sm[F_STAGE + row0 * ST_PITCH + c0col + 1]       = d[nt][1];
        sm[F_STAGE + (row0 + 8) * ST_PITCH + c0col]     = d[nt][2];
        sm[F_STAGE + (row0 + 8) * ST_PITCH + c0col + 1] = d[nt][3];
    }
    __syncthreads();
    float* o1 = out + (size_t)NBATCH * 64 + (size_t)blockIdx.x * (TILE_M * 64);
    for (int i = 4 * tid; i < TILE_M * 64; i += 4 * NTHREADS) {
        int r = i >> 6, c = i & 63;
        *(float4*)(o1 + i) = *(const float4*)&sm[F_STAGE + r * ST_PITCH + c];
    }
}

extern "C" void kernel_launch(void* const* d_in, const int* in_sizes, int n_in,
                              void* d_out, int out_size) {
    const float* x       = (const float*)d_in[0];
    const float* u_raw   = (const float*)d_in[1];
    const float* w_raw   = (const float*)d_in[2];
    const float* W_down  = (const float*)d_in[3];
    const float* b_down  = (const float*)d_in[4];
    const float* W_drift = (const float*)d_in[5];
    const float* b_drift = (const float*)d_in[6];
    const float* W1      = (const float*)d_in[7];
    const float* b1      = (const float*)d_in[8];
    const float* W2      = (const float*)d_in[9];
    const float* b2      = (const float*)d_in[10];
    float* out = (float*)d_out;

    noise_kernel<<<(NDEPTH * 64 + 255) / 256, 256>>>(u_raw, w_raw);

    cudaFuncSetAttribute(sdenet_mma,
                         cudaFuncAttributeMaxDynamicSharedMemorySize, SMEM_BYTES);
    sdenet_mma<<<NBATCH / TILE_M, NTHREADS, SMEM_BYTES>>>(
        x, W_down, b_down, W_drift, b_drift, W1, b1, W2, b2, out);
}